// round 2
// baseline (speedup 1.0000x reference)
#include <cuda_runtime.h>
#include <cuda_bf16.h>
#include <math.h>

// Problem constants
#define NN    8192
#define D_IN  512
#define HH    256
#define EE    262144
#define NL    2
#define LN_EPS 1e-5f

// ---------------- device scratch (no allocations allowed) ----------------
__device__ float g_hw[NN * HH];          // h @ W_gat[l]^T
__device__ float g_s_src[NN];
__device__ float g_s_tgt[NN];
__device__ int   g_deg[NN];
__device__ int   g_off[NN + 1];
__device__ int   g_cur[NN];
__device__ int   g_csr[EE];              // tgt indices grouped by src
__device__ float g_colsum_part[64 * HH];
__device__ float g_colsum[HH];
__device__ float g_pool_part[64 * HH];

// ---------------- GEMM: C[M x Nn] = A[M x K] * B[Nn x K]^T + bias -------
// BM=128, BN=64, BK=32, 256 threads, 8x4 microtile.
#define BM 128
#define BN 64
#define BK 32

__global__ __launch_bounds__(256, 2)
void gemm_nt(const float* __restrict__ A, const float* __restrict__ B,
             const float* __restrict__ bias, float* __restrict__ C,
             int M, int Nn, int K) {
    __shared__ float As[BM][BK + 1];
    __shared__ float Bs[BN][BK + 1];
    int t  = threadIdx.x;
    int tx = t & 15;          // 16 -> covers BN via 4 each
    int ty = t >> 4;          // 16 -> covers BM via 8 each
    int bm = blockIdx.x * BM;
    int bn = blockIdx.y * BN;

    float acc[8][4];
#pragma unroll
    for (int m = 0; m < 8; m++)
#pragma unroll
        for (int n = 0; n < 4; n++) acc[m][n] = 0.f;

    for (int k0 = 0; k0 < K; k0 += BK) {
        // load A tile: 128x32 = 1024 float4, 4 per thread
#pragma unroll
        for (int q = 0; q < 4; q++) {
            int idx = t + q * 256;
            int r = idx >> 3, c4 = idx & 7;
            float4 v = *(const float4*)(A + (size_t)(bm + r) * K + k0 + c4 * 4);
            As[r][c4 * 4 + 0] = v.x; As[r][c4 * 4 + 1] = v.y;
            As[r][c4 * 4 + 2] = v.z; As[r][c4 * 4 + 3] = v.w;
        }
        // load B tile: 64x32 = 512 float4, 2 per thread
#pragma unroll
        for (int q = 0; q < 2; q++) {
            int idx = t + q * 256;
            int r = idx >> 3, c4 = idx & 7;
            float4 v = *(const float4*)(B + (size_t)(bn + r) * K + k0 + c4 * 4);
            Bs[r][c4 * 4 + 0] = v.x; Bs[r][c4 * 4 + 1] = v.y;
            Bs[r][c4 * 4 + 2] = v.z; Bs[r][c4 * 4 + 3] = v.w;
        }
        __syncthreads();
#pragma unroll
        for (int kk = 0; kk < BK; kk++) {
            float a[8], b[4];
#pragma unroll
            for (int m = 0; m < 8; m++) a[m] = As[ty * 8 + m][kk];
#pragma unroll
            for (int n = 0; n < 4; n++) b[n] = Bs[tx * 4 + n][kk];
#pragma unroll
            for (int m = 0; m < 8; m++)
#pragma unroll
                for (int n = 0; n < 4; n++) acc[m][n] = fmaf(a[m], b[n], acc[m][n]);
        }
        __syncthreads();
    }
#pragma unroll
    for (int m = 0; m < 8; m++) {
        int row = bm + ty * 8 + m;
#pragma unroll
        for (int n = 0; n < 4; n++) {
            int col = bn + tx * 4 + n;
            float v = acc[m][n];
            if (bias) v += bias[col];
            C[(size_t)row * Nn + col] = v;
        }
    }
}

// ---------------- CSR build (once per launch) ----------------------------
__global__ void zero_deg_kernel() {
    int i = blockIdx.x * blockDim.x + threadIdx.x;
    if (i < NN) g_deg[i] = 0;
}

__global__ void csr_hist_kernel(const int* __restrict__ ei) {
    for (int k = blockIdx.x * blockDim.x + threadIdx.x; k < EE;
         k += gridDim.x * blockDim.x) {
        atomicAdd(&g_deg[ei[k]], 1);  // src row
    }
}

__global__ void csr_scan_kernel() {
    __shared__ int sums[1024];
    int t = threadIdx.x;
    int base = t * 8;
    int loc[8];
    int s = 0;
#pragma unroll
    for (int j = 0; j < 8; j++) { loc[j] = s; s += g_deg[base + j]; }
    sums[t] = s;
    __syncthreads();
    for (int off = 1; off < 1024; off <<= 1) {
        int v = (t >= off) ? sums[t - off] : 0;
        __syncthreads();
        sums[t] += v;
        __syncthreads();
    }
    int pre = (t > 0) ? sums[t - 1] : 0;
#pragma unroll
    for (int j = 0; j < 8; j++) {
        g_off[base + j] = pre + loc[j];
        g_cur[base + j] = pre + loc[j];
    }
    if (t == 0) g_off[NN] = sums[1023];
}

__global__ void csr_scatter_kernel(const int* __restrict__ ei) {
    const int* src = ei;
    const int* tgt = ei + EE;
    for (int k = blockIdx.x * blockDim.x + threadIdx.x; k < EE;
         k += gridDim.x * blockDim.x) {
        int pos = atomicAdd(&g_cur[src[k]], 1);
        g_csr[pos] = tgt[k];
    }
}

// Sort each node's target list (edges are unique (src,tgt) -> tgt unique per src),
// so aggregation order is deterministic regardless of atomic scatter order.
__global__ void csr_sort_kernel() {
    int i = blockIdx.x;
    int beg = g_off[i], end = g_off[i + 1];
    int deg = end - beg;
    if (deg <= 1 || deg > 1024) return;
    __shared__ int buf[1024];
    for (int j = threadIdx.x; j < deg; j += blockDim.x) buf[j] = g_csr[beg + j];
    __syncthreads();
    for (int p = 0; p < deg; p++) {
        int start = p & 1;
        for (int j = threadIdx.x; 2 * j + start + 1 < deg; j += blockDim.x) {
            int a = buf[2 * j + start], b = buf[2 * j + start + 1];
            if (a > b) { buf[2 * j + start] = b; buf[2 * j + start + 1] = a; }
        }
        __syncthreads();
    }
    for (int j = threadIdx.x; j < deg; j += blockDim.x) g_csr[beg + j] = buf[j];
}

// ---------------- per-node attention scores ------------------------------
__global__ void scores_kernel(const float* __restrict__ a) {
    int gid  = blockIdx.x * blockDim.x + threadIdx.x;
    int node = gid >> 5;
    int lane = gid & 31;
    if (node >= NN) return;
    const float* row = g_hw + (size_t)node * HH;
    float s1 = 0.f, s2 = 0.f;
    for (int j = lane; j < HH; j += 32) {
        float v = row[j];
        s1 += v * a[j];
        s2 += v * a[HH + j];
    }
#pragma unroll
    for (int o = 16; o; o >>= 1) {
        s1 += __shfl_xor_sync(0xffffffffu, s1, o);
        s2 += __shfl_xor_sync(0xffffffffu, s2, o);
    }
    if (lane == 0) { g_s_src[node] = s1; g_s_tgt[node] = s2; }
}

// ---------------- column sum of hw (two stage, deterministic) ------------
__global__ void colsum1_kernel() {
    int b = blockIdx.x;       // 64 blocks
    int c = threadIdx.x;      // 256
    int r0 = b * (NN / 64);
    float s = 0.f;
    for (int r = 0; r < NN / 64; r++) s += g_hw[(size_t)(r0 + r) * HH + c];
    g_colsum_part[b * HH + c] = s;
}
__global__ void colsum2_kernel() {
    int c = threadIdx.x;
    float s = 0.f;
    for (int b = 0; b < 64; b++) s += g_colsum_part[b * HH + c];
    g_colsum[c] = s;
}

// ---------------- sparse aggregate + residual + LayerNorm + ELU ----------
__global__ void aggregate_kernel(float* __restrict__ h,
                                 const float* __restrict__ lng,
                                 const float* __restrict__ lnb) {
    int i = blockIdx.x;
    int c = threadIdx.x;      // 256 = H channels
    __shared__ int   st[256];
    __shared__ float sw[256];
    __shared__ float red[256];
    __shared__ float sh_d;

    int beg = g_off[i], end = g_off[i + 1];
    float si = g_s_src[i];
    float acc = 0.f;

    float wsum_all = 0.f;
    for (int base = beg; base < end; base += 256) {
        int len = min(256, end - base);
        float w = 0.f;
        if (c < len) {
            int t = g_csr[base + c];
            st[c] = t;
            float e = si + g_s_tgt[t];
            e = (e > 0.f) ? e : 0.2f * e;
            w = expf(e) - 1.f;
            sw[c] = w;
        }
        __syncthreads();
        for (int k = 0; k < len; k++)
            acc = fmaf(sw[k], g_hw[(size_t)st[k] * HH + c], acc);
        // block-reduce chunk weight sum (deterministic tree)
        red[c] = w;
        __syncthreads();
#pragma unroll
        for (int o = 128; o > 0; o >>= 1) {
            if (c < o) red[c] += red[c + o];
            __syncthreads();
        }
        wsum_all += red[0];
        __syncthreads();
    }
    if (c == 0) sh_d = (float)NN + wsum_all;
    __syncthreads();

    float hn = (g_colsum[c] + acc) / sh_d;
    float v  = h[(size_t)i * HH + c] + hn;

    // LayerNorm over H=256 (deterministic tree reduce)
    red[c] = v;
    __syncthreads();
#pragma unroll
    for (int o = 128; o > 0; o >>= 1) {
        if (c < o) red[c] += red[c + o];
        __syncthreads();
    }
    float mu = red[0] / (float)HH;
    __syncthreads();
    float d = v - mu;
    red[c] = d * d;
    __syncthreads();
#pragma unroll
    for (int o = 128; o > 0; o >>= 1) {
        if (c < o) red[c] += red[c + o];
        __syncthreads();
    }
    float var = red[0] / (float)HH;
    float y = (v - mu) * rsqrtf(var + LN_EPS) * lng[c] + lnb[c];
    y = (y > 0.f) ? y : (expf(y) - 1.f);   // ELU
    h[(size_t)i * HH + c] = y;
}

// ---------------- gated pooling ------------------------------------------
__global__ void pool1_kernel(const float* __restrict__ h,
                             const float* __restrict__ Wp,
                             const float* __restrict__ bp) {
    __shared__ float gates[128];
    int b = blockIdx.x;       // 64 blocks x 128 nodes
    int t = threadIdx.x;
    int warp = t >> 5, lane = t & 31;
    int base = b * 128;
    for (int it = 0; it < 16; it++) {
        int n = base + warp * 16 + it;
        const float* row = h + (size_t)n * HH;
        float s = 0.f;
        for (int j = lane; j < HH; j += 32) s += row[j] * Wp[j];
#pragma unroll
        for (int o = 16; o; o >>= 1) s += __shfl_xor_sync(0xffffffffu, s, o);
        if (lane == 0) gates[warp * 16 + it] = 1.f / (1.f + expf(-(s + bp[0])));
    }
    __syncthreads();
    int c = t;                // 256 channels
    float s = 0.f;
    for (int ln = 0; ln < 128; ln++)
        s = fmaf(gates[ln], h[(size_t)(base + ln) * HH + c], s);
    g_pool_part[b * HH + c] = s;
}
__global__ void pool2_kernel(float* __restrict__ emb) {
    int c = threadIdx.x;
    float s = 0.f;
    for (int b = 0; b < 64; b++) s += g_pool_part[b * HH + c];
    emb[c] = s;
}

// ---------------- launch --------------------------------------------------
extern "C" void kernel_launch(void* const* d_in, const int* in_sizes, int n_in,
                              void* d_out, int out_size) {
    const float* x      = (const float*)d_in[0];
    const int*   ei     = (const int*)d_in[1];
    const float* W_in   = (const float*)d_in[2];
    const float* b_in   = (const float*)d_in[3];
    const float* W_gat  = (const float*)d_in[4];
    const float* a_gat  = (const float*)d_in[5];
    const float* ln_g   = (const float*)d_in[6];
    const float* ln_b   = (const float*)d_in[7];
    const float* W_pool = (const float*)d_in[8];
    const float* b_pool = (const float*)d_in[9];

    float* out = (float*)d_out;
    float* h   = out;                  // h lives in d_out[0 : N*H]

    float* hw_ptr = nullptr;
    cudaGetSymbolAddress((void**)&hw_ptr, g_hw);

    // input projection: h = x @ W_in^T + b_in   [8192x512]x[256x512]^T
    zero_deg_kernel<<<NN / 256, 256>>>();
    gemm_nt<<<dim3(NN / BM, HH / BN), 256>>>(x, W_in, b_in, h, NN, HH, D_IN);

    // CSR build (edge structure is launch-invariant but rebuilt each call)
    csr_hist_kernel<<<256, 256>>>(ei);
    csr_scan_kernel<<<1, 1024>>>();
    csr_scatter_kernel<<<256, 256>>>(ei);
    csr_sort_kernel<<<NN, 128>>>();

    for (int l = 0; l < NL; l++) {
        gemm_nt<<<dim3(NN / BM, HH / BN), 256>>>(h, W_gat + (size_t)l * HH * HH,
                                                 nullptr, hw_ptr, NN, HH, HH);
        scores_kernel<<<NN / 8, 256>>>(a_gat + (size_t)l * 2 * HH);
        colsum1_kernel<<<64, 256>>>();
        colsum2_kernel<<<1, 256>>>();
        aggregate_kernel<<<NN, 256>>>(h, ln_g + (size_t)l * HH, ln_b + (size_t)l * HH);
    }

    pool1_kernel<<<64, 256>>>(h, W_pool, b_pool);
    pool2_kernel<<<1, 256>>>(out + (size_t)NN * HH);
}

// round 3
// speedup vs baseline: 1.8791x; 1.8791x over previous
#include <cuda_runtime.h>
#include <cuda_bf16.h>
#include <math.h>

// Problem constants
#define NN    8192
#define D_IN  512
#define HH    256
#define EE    262144
#define NL    2
#define LN_EPS 1e-5f

// ---------------- device scratch (no allocations allowed) ----------------
__device__ float g_hw[NN * HH];          // h @ W_gat[l]^T
__device__ float g_s_src[NN];
__device__ float g_s_tgt[NN];
__device__ int   g_deg[NN];
__device__ int   g_off[NN + 1];
__device__ int   g_cur[NN];
__device__ int   g_csr[EE];              // tgt indices grouped by src
__device__ float g_colsum_part[64 * HH];
__device__ float g_colsum[HH];
__device__ float g_pool_part[64 * HH];

// ---------------- GEMM: C[M x Nn] = A[M x K] * B[Nn x K]^T + bias -------
// 128x128x16 block tile, 256 threads, 8x8 microtile, double-buffered smem.
#define GBM 128
#define GBN 128
#define GBK 16
#define GPAD 4

__global__ __launch_bounds__(256)
void gemm_nt(const float* __restrict__ A, const float* __restrict__ B,
             const float* __restrict__ bias, float* __restrict__ C,
             int M, int Nn, int K) {
    __shared__ float As[2][GBK][GBM + GPAD];
    __shared__ float Bs[2][GBK][GBN + GPAD];
    int t  = threadIdx.x;
    int tx = t & 15;          // column group: 16 * 8 = 128
    int ty = t >> 4;          // row group:    16 * 8 = 128
    int bm = blockIdx.x * GBM;
    int bn = blockIdx.y * GBN;

    // loader mapping: each thread loads 2 float4 per matrix per tile
    int la_r = t >> 2;            // 0..63
    int la_k = (t & 3) << 2;      // 0,4,8,12

    float acc[8][8];
#pragma unroll
    for (int m = 0; m < 8; m++)
#pragma unroll
        for (int n = 0; n < 8; n++) acc[m][n] = 0.f;

    const int KT = K / GBK;

    // preload tile 0
    {
        const float* Ap0 = A + (size_t)(bm + la_r) * K + la_k;
        const float* Ap1 = A + (size_t)(bm + la_r + 64) * K + la_k;
        const float* Bp0 = B + (size_t)(bn + la_r) * K + la_k;
        const float* Bp1 = B + (size_t)(bn + la_r + 64) * K + la_k;
        float4 a0 = *(const float4*)Ap0;
        float4 a1 = *(const float4*)Ap1;
        float4 b0 = *(const float4*)Bp0;
        float4 b1 = *(const float4*)Bp1;
        As[0][la_k + 0][la_r]      = a0.x; As[0][la_k + 1][la_r]      = a0.y;
        As[0][la_k + 2][la_r]      = a0.z; As[0][la_k + 3][la_r]      = a0.w;
        As[0][la_k + 0][la_r + 64] = a1.x; As[0][la_k + 1][la_r + 64] = a1.y;
        As[0][la_k + 2][la_r + 64] = a1.z; As[0][la_k + 3][la_r + 64] = a1.w;
        Bs[0][la_k + 0][la_r]      = b0.x; Bs[0][la_k + 1][la_r]      = b0.y;
        Bs[0][la_k + 2][la_r]      = b0.z; Bs[0][la_k + 3][la_r]      = b0.w;
        Bs[0][la_k + 0][la_r + 64] = b1.x; Bs[0][la_k + 1][la_r + 64] = b1.y;
        Bs[0][la_k + 2][la_r + 64] = b1.z; Bs[0][la_k + 3][la_r + 64] = b1.w;
    }
    __syncthreads();

    for (int kt = 0; kt < KT; kt++) {
        int cur = kt & 1;
        bool has = (kt + 1) < KT;
        float4 pa0, pa1, pb0, pb1;
        if (has) {
            int k0 = (kt + 1) * GBK;
            pa0 = *(const float4*)(A + (size_t)(bm + la_r) * K + k0 + la_k);
            pa1 = *(const float4*)(A + (size_t)(bm + la_r + 64) * K + k0 + la_k);
            pb0 = *(const float4*)(B + (size_t)(bn + la_r) * K + k0 + la_k);
            pb1 = *(const float4*)(B + (size_t)(bn + la_r + 64) * K + k0 + la_k);
        }
#pragma unroll
        for (int kk = 0; kk < GBK; kk++) {
            float4 a0 = *(const float4*)&As[cur][kk][ty * 8];
            float4 a1 = *(const float4*)&As[cur][kk][ty * 8 + 4];
            float4 b0 = *(const float4*)&Bs[cur][kk][tx * 8];
            float4 b1 = *(const float4*)&Bs[cur][kk][tx * 8 + 4];
            float a[8] = {a0.x, a0.y, a0.z, a0.w, a1.x, a1.y, a1.z, a1.w};
            float b[8] = {b0.x, b0.y, b0.z, b0.w, b1.x, b1.y, b1.z, b1.w};
#pragma unroll
            for (int m = 0; m < 8; m++)
#pragma unroll
                for (int n = 0; n < 8; n++)
                    acc[m][n] = fmaf(a[m], b[n], acc[m][n]);
        }
        if (has) {
            int nxt = 1 - cur;
            As[nxt][la_k + 0][la_r]      = pa0.x; As[nxt][la_k + 1][la_r]      = pa0.y;
            As[nxt][la_k + 2][la_r]      = pa0.z; As[nxt][la_k + 3][la_r]      = pa0.w;
            As[nxt][la_k + 0][la_r + 64] = pa1.x; As[nxt][la_k + 1][la_r + 64] = pa1.y;
            As[nxt][la_k + 2][la_r + 64] = pa1.z; As[nxt][la_k + 3][la_r + 64] = pa1.w;
            Bs[nxt][la_k + 0][la_r]      = pb0.x; Bs[nxt][la_k + 1][la_r]      = pb0.y;
            Bs[nxt][la_k + 2][la_r]      = pb0.z; Bs[nxt][la_k + 3][la_r]      = pb0.w;
            Bs[nxt][la_k + 0][la_r + 64] = pb1.x; Bs[nxt][la_k + 1][la_r + 64] = pb1.y;
            Bs[nxt][la_k + 2][la_r + 64] = pb1.z; Bs[nxt][la_k + 3][la_r + 64] = pb1.w;
        }
        __syncthreads();
    }

#pragma unroll
    for (int m = 0; m < 8; m++) {
        int row = bm + ty * 8 + m;
        float4 o0, o1;
        int c0 = bn + tx * 8;
        o0.x = acc[m][0]; o0.y = acc[m][1]; o0.z = acc[m][2]; o0.w = acc[m][3];
        o1.x = acc[m][4]; o1.y = acc[m][5]; o1.z = acc[m][6]; o1.w = acc[m][7];
        if (bias) {
            o0.x += bias[c0 + 0]; o0.y += bias[c0 + 1];
            o0.z += bias[c0 + 2]; o0.w += bias[c0 + 3];
            o1.x += bias[c0 + 4]; o1.y += bias[c0 + 5];
            o1.z += bias[c0 + 6]; o1.w += bias[c0 + 7];
        }
        *(float4*)(C + (size_t)row * Nn + c0)     = o0;
        *(float4*)(C + (size_t)row * Nn + c0 + 4) = o1;
    }
}

// ---------------- CSR build (once per launch) ----------------------------
__global__ void zero_deg_kernel() {
    int i = blockIdx.x * blockDim.x + threadIdx.x;
    if (i < NN) g_deg[i] = 0;
}

__global__ void csr_hist_kernel(const int* __restrict__ ei) {
    for (int k = blockIdx.x * blockDim.x + threadIdx.x; k < EE;
         k += gridDim.x * blockDim.x) {
        atomicAdd(&g_deg[ei[k]], 1);  // src row
    }
}

// 1024 threads, 8 elems each; warp-shuffle scan, 2 barriers total.
__global__ void csr_scan_kernel() {
    __shared__ int wsum[32];
    int t = threadIdx.x;
    int lane = t & 31, warp = t >> 5;
    int base = t * 8;
    int loc[8];
    int s = 0;
#pragma unroll
    for (int j = 0; j < 8; j++) { loc[j] = s; s += g_deg[base + j]; }
    int v = s;
#pragma unroll
    for (int o = 1; o < 32; o <<= 1) {
        int u = __shfl_up_sync(0xffffffffu, v, o);
        if (lane >= o) v += u;
    }
    if (lane == 31) wsum[warp] = v;
    __syncthreads();
    if (warp == 0) {
        int w = wsum[lane];
#pragma unroll
        for (int o = 1; o < 32; o <<= 1) {
            int u = __shfl_up_sync(0xffffffffu, w, o);
            if (lane >= o) w += u;
        }
        wsum[lane] = w;
    }
    __syncthreads();
    int pre = v - s + (warp ? wsum[warp - 1] : 0);
#pragma unroll
    for (int j = 0; j < 8; j++) {
        g_off[base + j] = pre + loc[j];
        g_cur[base + j] = pre + loc[j];
    }
    if (t == 1023) g_off[NN] = wsum[31];
}

__global__ void csr_scatter_kernel(const int* __restrict__ ei) {
    const int* src = ei;
    const int* tgt = ei + EE;
    for (int k = blockIdx.x * blockDim.x + threadIdx.x; k < EE;
         k += gridDim.x * blockDim.x) {
        int pos = atomicAdd(&g_cur[src[k]], 1);
        g_csr[pos] = tgt[k];
    }
}

// Sort each node's target list -> deterministic aggregation order.
__global__ void csr_sort_kernel() {
    int i = blockIdx.x;
    int beg = g_off[i], end = g_off[i + 1];
    int deg = end - beg;
    if (deg <= 1 || deg > 1024) return;
    __shared__ int buf[1024];
    for (int j = threadIdx.x; j < deg; j += blockDim.x) buf[j] = g_csr[beg + j];
    __syncthreads();
    for (int p = 0; p < deg; p++) {
        int start = p & 1;
        for (int j = threadIdx.x; 2 * j + start + 1 < deg; j += blockDim.x) {
            int a = buf[2 * j + start], b = buf[2 * j + start + 1];
            if (a > b) { buf[2 * j + start] = b; buf[2 * j + start + 1] = a; }
        }
        __syncthreads();
    }
    for (int j = threadIdx.x; j < deg; j += blockDim.x) g_csr[beg + j] = buf[j];
}

// ---------------- per-node attention scores ------------------------------
__global__ void scores_kernel(const float* __restrict__ a) {
    int gid  = blockIdx.x * blockDim.x + threadIdx.x;
    int node = gid >> 5;
    int lane = gid & 31;
    if (node >= NN) return;
    const float* row = g_hw + (size_t)node * HH;
    float s1 = 0.f, s2 = 0.f;
    for (int j = lane; j < HH; j += 32) {
        float v = row[j];
        s1 += v * a[j];
        s2 += v * a[HH + j];
    }
#pragma unroll
    for (int o = 16; o; o >>= 1) {
        s1 += __shfl_xor_sync(0xffffffffu, s1, o);
        s2 += __shfl_xor_sync(0xffffffffu, s2, o);
    }
    if (lane == 0) { g_s_src[node] = s1; g_s_tgt[node] = s2; }
}

// ---------------- column sum of hw (two stage, deterministic) ------------
__global__ void colsum1_kernel() {
    int b = blockIdx.x;       // 64 blocks
    int c = threadIdx.x;      // 256
    int r0 = b * (NN / 64);
    float s = 0.f;
    for (int r = 0; r < NN / 64; r++) s += g_hw[(size_t)(r0 + r) * HH + c];
    g_colsum_part[b * HH + c] = s;
}
__global__ void colsum2_kernel() {
    int c = threadIdx.x;
    float s = 0.f;
    for (int b = 0; b < 64; b++) s += g_colsum_part[b * HH + c];
    g_colsum[c] = s;
}

// ---------------- sparse aggregate + residual + LayerNorm + ELU ----------
// 64 threads, each owns 4 channels (float4).
__global__ void aggregate_kernel(float* __restrict__ h,
                                 const float* __restrict__ lng,
                                 const float* __restrict__ lnb) {
    int i = blockIdx.x;
    int t = threadIdx.x;      // 64
    __shared__ int   st[64];
    __shared__ float sw[64];
    __shared__ float red[64];

    int beg = g_off[i], end = g_off[i + 1];
    float si = g_s_src[i];
    float4 acc = make_float4(0.f, 0.f, 0.f, 0.f);
    float wsum_all = 0.f;

    for (int base = beg; base < end; base += 64) {
        int len = min(64, end - base);
        float w = 0.f;
        if (t < len) {
            int tg = g_csr[base + t];
            st[t] = tg;
            float e = si + g_s_tgt[tg];
            e = (e > 0.f) ? e : 0.2f * e;
            w = expf(e) - 1.f;
            sw[t] = w;
        }
        __syncthreads();
        int k = 0;
        for (; k + 3 < len; k += 4) {
            const float4* r0 = (const float4*)(g_hw + (size_t)st[k] * HH) + t;
            const float4* r1 = (const float4*)(g_hw + (size_t)st[k + 1] * HH) + t;
            const float4* r2 = (const float4*)(g_hw + (size_t)st[k + 2] * HH) + t;
            const float4* r3 = (const float4*)(g_hw + (size_t)st[k + 3] * HH) + t;
            float4 v0 = *r0, v1 = *r1, v2 = *r2, v3 = *r3;
            float w0 = sw[k], w1 = sw[k + 1], w2 = sw[k + 2], w3 = sw[k + 3];
            acc.x = fmaf(w0, v0.x, acc.x); acc.y = fmaf(w0, v0.y, acc.y);
            acc.z = fmaf(w0, v0.z, acc.z); acc.w = fmaf(w0, v0.w, acc.w);
            acc.x = fmaf(w1, v1.x, acc.x); acc.y = fmaf(w1, v1.y, acc.y);
            acc.z = fmaf(w1, v1.z, acc.z); acc.w = fmaf(w1, v1.w, acc.w);
            acc.x = fmaf(w2, v2.x, acc.x); acc.y = fmaf(w2, v2.y, acc.y);
            acc.z = fmaf(w2, v2.z, acc.z); acc.w = fmaf(w2, v2.w, acc.w);
            acc.x = fmaf(w3, v3.x, acc.x); acc.y = fmaf(w3, v3.y, acc.y);
            acc.z = fmaf(w3, v3.z, acc.z); acc.w = fmaf(w3, v3.w, acc.w);
        }
        for (; k < len; k++) {
            float4 v = *((const float4*)(g_hw + (size_t)st[k] * HH) + t);
            float wk = sw[k];
            acc.x = fmaf(wk, v.x, acc.x); acc.y = fmaf(wk, v.y, acc.y);
            acc.z = fmaf(wk, v.z, acc.z); acc.w = fmaf(wk, v.w, acc.w);
        }
        // chunk weight sum (deterministic tree)
        red[t] = w;
        __syncthreads();
#pragma unroll
        for (int o = 32; o > 0; o >>= 1) {
            if (t < o) red[t] += red[t + o];
            __syncthreads();
        }
        wsum_all += red[0];
        __syncthreads();
    }
    float denom = (float)NN + wsum_all;

    float4 cs = *((const float4*)g_colsum + t);
    float4 hv = *((const float4*)(h + (size_t)i * HH) + t);
    float4 v;
    v.x = hv.x + (cs.x + acc.x) / denom;
    v.y = hv.y + (cs.y + acc.y) / denom;
    v.z = hv.z + (cs.z + acc.z) / denom;
    v.w = hv.w + (cs.w + acc.w) / denom;

    // LayerNorm over H=256
    red[t] = v.x + v.y + v.z + v.w;
    __syncthreads();
#pragma unroll
    for (int o = 32; o > 0; o >>= 1) {
        if (t < o) red[t] += red[t + o];
        __syncthreads();
    }
    float mu = red[0] / (float)HH;
    __syncthreads();
    float dx = v.x - mu, dy = v.y - mu, dz = v.z - mu, dw = v.w - mu;
    red[t] = dx * dx + dy * dy + dz * dz + dw * dw;
    __syncthreads();
#pragma unroll
    for (int o = 32; o > 0; o >>= 1) {
        if (t < o) red[t] += red[t + o];
        __syncthreads();
    }
    float rs = rsqrtf(red[0] / (float)HH + LN_EPS);
    float4 g = *((const float4*)lng + t);
    float4 b = *((const float4*)lnb + t);
    float4 y;
    y.x = dx * rs * g.x + b.x;
    y.y = dy * rs * g.y + b.y;
    y.z = dz * rs * g.z + b.z;
    y.w = dw * rs * g.w + b.w;
    y.x = (y.x > 0.f) ? y.x : (expf(y.x) - 1.f);
    y.y = (y.y > 0.f) ? y.y : (expf(y.y) - 1.f);
    y.z = (y.z > 0.f) ? y.z : (expf(y.z) - 1.f);
    y.w = (y.w > 0.f) ? y.w : (expf(y.w) - 1.f);
    *((float4*)(h + (size_t)i * HH) + t) = y;
}

// ---------------- gated pooling ------------------------------------------
__global__ void pool1_kernel(const float* __restrict__ h,
                             const float* __restrict__ Wp,
                             const float* __restrict__ bp) {
    __shared__ float gates[128];
    int b = blockIdx.x;       // 64 blocks x 128 nodes
    int t = threadIdx.x;
    int warp = t >> 5, lane = t & 31;
    int base = b * 128;
    for (int it = 0; it < 16; it++) {
        int n = base + warp * 16 + it;
        const float* row = h + (size_t)n * HH;
        float s = 0.f;
        for (int j = lane; j < HH; j += 32) s += row[j] * Wp[j];
#pragma unroll
        for (int o = 16; o; o >>= 1) s += __shfl_xor_sync(0xffffffffu, s, o);
        if (lane == 0) gates[warp * 16 + it] = 1.f / (1.f + expf(-(s + bp[0])));
    }
    __syncthreads();
    int c = t;                // 256 channels
    float s = 0.f;
    for (int ln = 0; ln < 128; ln++)
        s = fmaf(gates[ln], h[(size_t)(base + ln) * HH + c], s);
    g_pool_part[b * HH + c] = s;
}
__global__ void pool2_kernel(float* __restrict__ emb) {
    int c = threadIdx.x;
    float s = 0.f;
    for (int b = 0; b < 64; b++) s += g_pool_part[b * HH + c];
    emb[c] = s;
}

// ---------------- launch --------------------------------------------------
extern "C" void kernel_launch(void* const* d_in, const int* in_sizes, int n_in,
                              void* d_out, int out_size) {
    const float* x      = (const float*)d_in[0];
    const int*   ei     = (const int*)d_in[1];
    const float* W_in   = (const float*)d_in[2];
    const float* b_in   = (const float*)d_in[3];
    const float* W_gat  = (const float*)d_in[4];
    const float* a_gat  = (const float*)d_in[5];
    const float* ln_g   = (const float*)d_in[6];
    const float* ln_b   = (const float*)d_in[7];
    const float* W_pool = (const float*)d_in[8];
    const float* b_pool = (const float*)d_in[9];

    float* out = (float*)d_out;
    float* h   = out;                  // h lives in d_out[0 : N*H]

    float* hw_ptr = nullptr;
    cudaGetSymbolAddress((void**)&hw_ptr, g_hw);

    // input projection: h = x @ W_in^T + b_in   [8192x512]x[256x512]^T
    zero_deg_kernel<<<NN / 256, 256>>>();
    gemm_nt<<<dim3(NN / GBM, HH / GBN), 256>>>(x, W_in, b_in, h, NN, HH, D_IN);

    // CSR build
    csr_hist_kernel<<<256, 256>>>(ei);
    csr_scan_kernel<<<1, 1024>>>();
    csr_scatter_kernel<<<256, 256>>>(ei);
    csr_sort_kernel<<<NN, 128>>>();

    for (int l = 0; l < NL; l++) {
        gemm_nt<<<dim3(NN / GBM, HH / GBN), 256>>>(h, W_gat + (size_t)l * HH * HH,
                                                   nullptr, hw_ptr, NN, HH, HH);
        scores_kernel<<<NN / 8, 256>>>(a_gat + (size_t)l * 2 * HH);
        colsum1_kernel<<<64, 256>>>();
        colsum2_kernel<<<1, 256>>>();
        aggregate_kernel<<<NN, 64>>>(h, ln_g + (size_t)l * HH, ln_b + (size_t)l * HH);
    }

    pool1_kernel<<<64, 256>>>(h, W_pool, b_pool);
    pool2_kernel<<<1, 256>>>(out + (size_t)NN * HH);
}

// round 6
// speedup vs baseline: 2.1057x; 1.1206x over previous
#include <cuda_runtime.h>
#include <cuda_bf16.h>
#include <math.h>
#include <stdint.h>

// Problem constants
#define NN    8192
#define D_IN  512
#define HH    256
#define EE    262144
#define NL    2
#define LN_EPS 1e-5f

// ---------------- device scratch (no allocations allowed) ----------------
__device__ float g_hw[NN * HH];                 // h @ W_gat[l]^T (fp32)
__device__ __nv_bfloat16 g_hwb[NN * HH];        // bf16 copy for gathers
__device__ __nv_bfloat16 g_Ah[NN * D_IN];       // x split hi
__device__ __nv_bfloat16 g_Al[NN * D_IN];       // x split lo
__device__ __nv_bfloat16 g_Ah2[NN * HH];        // h split hi
__device__ __nv_bfloat16 g_Al2[NN * HH];        // h split lo
__device__ __nv_bfloat16 g_Bh[D_IN * HH + NL * HH * HH];  // weights hi
__device__ __nv_bfloat16 g_Bl[D_IN * HH + NL * HH * HH];  // weights lo
__device__ float g_s_src[NN];
__device__ float g_s_tgt[NN];
__device__ int   g_deg[NN];
__device__ int   g_off[NN + 1];
__device__ int   g_cur[NN];
__device__ int   g_csr[EE];
__device__ float g_colsum_part[64 * HH];
__device__ float g_colsum[HH];
__device__ float g_pool_part[64 * HH];

// ---------------- HMMA GEMM: C[8192 x 256] = A * B^T ---------------------
// Block 128x128, 8 warps (2x4), warp tile 64x32.
// bf16 split inputs, 3 accumulating passes, fp32 accum.
#define SROW 40     // smem row stride in bf16 (conflict-free fragment loads)

__device__ __forceinline__ uint32_t lds32(const __nv_bfloat16* p) {
    return *(const uint32_t*)p;
}
__device__ __forceinline__ void mma_bf16(float* d, const uint32_t* a, const uint32_t* b) {
    asm volatile(
        "mma.sync.aligned.m16n8k16.row.col.f32.bf16.bf16.f32 "
        "{%0,%1,%2,%3}, {%4,%5,%6,%7}, {%8,%9}, {%0,%1,%2,%3};"
        : "+f"(d[0]), "+f"(d[1]), "+f"(d[2]), "+f"(d[3])
        : "r"(a[0]), "r"(a[1]), "r"(a[2]), "r"(a[3]), "r"(b[0]), "r"(b[1]));
}

__global__ __launch_bounds__(256)
void gemm_mma(const __nv_bfloat16* __restrict__ Ah, const __nv_bfloat16* __restrict__ Al,
              const __nv_bfloat16* __restrict__ Bh, const __nv_bfloat16* __restrict__ Bl,
              const float* __restrict__ bias, float* __restrict__ Cf,
              __nv_bfloat16* __restrict__ Chi, __nv_bfloat16* __restrict__ Clo,
              __nv_bfloat16* __restrict__ Cb, int K) {
    __shared__ __nv_bfloat16 sAh[128 * SROW];
    __shared__ __nv_bfloat16 sAl[128 * SROW];
    __shared__ __nv_bfloat16 sBh[128 * SROW];
    __shared__ __nv_bfloat16 sBl[128 * SROW];
    int tid = threadIdx.x;
    int wid = tid >> 5, lane = tid & 31;
    int wm = wid >> 2, wn = wid & 3;
    int bm = blockIdx.x * 128;
    int bn = blockIdx.y * 128;

    float acc[4][4][4];
#pragma unroll
    for (int mt = 0; mt < 4; mt++)
#pragma unroll
        for (int nt = 0; nt < 4; nt++)
#pragma unroll
            for (int q = 0; q < 4; q++) acc[mt][nt][q] = 0.f;

    const int NCH = K >> 5;   // 32-wide K chunks
    for (int kc = 0; kc < NCH; kc++) {
        // load 4 tiles of 128 rows x 32 bf16 (64B = 4 uint4 per row); 2 uint4/thread/tile
#pragma unroll
        for (int q = 0; q < 2; q++) {
            int idx = tid + q * 256;         // 0..511
            int r = idx >> 2, u = idx & 3;
            size_t ga = (size_t)(bm + r) * K + kc * 32 + u * 8;
            size_t gb = (size_t)(bn + r) * K + kc * 32 + u * 8;
            int so = r * SROW + u * 8;
            *(uint4*)&sAh[so] = *(const uint4*)(Ah + ga);
            *(uint4*)&sAl[so] = *(const uint4*)(Al + ga);
            *(uint4*)&sBh[so] = *(const uint4*)(Bh + gb);
            *(uint4*)&sBl[so] = *(const uint4*)(Bl + gb);
        }
        __syncthreads();
#pragma unroll
        for (int ks = 0; ks < 2; ks++) {
            int ar = wm * 64 + (lane >> 2);
            int ac = ks * 16 + (lane & 3) * 2;
            uint32_t ah[4][4], al[4][4], bh[4][2], bl[4][2];
#pragma unroll
            for (int mt = 0; mt < 4; mt++) {
                int r = ar + mt * 16;
                ah[mt][0] = lds32(&sAh[r * SROW + ac]);
                ah[mt][1] = lds32(&sAh[(r + 8) * SROW + ac]);
                ah[mt][2] = lds32(&sAh[r * SROW + ac + 8]);
                ah[mt][3] = lds32(&sAh[(r + 8) * SROW + ac + 8]);
                al[mt][0] = lds32(&sAl[r * SROW + ac]);
                al[mt][1] = lds32(&sAl[(r + 8) * SROW + ac]);
                al[mt][2] = lds32(&sAl[r * SROW + ac + 8]);
                al[mt][3] = lds32(&sAl[(r + 8) * SROW + ac + 8]);
            }
            int br = wn * 32 + (lane >> 2);
#pragma unroll
            for (int nt = 0; nt < 4; nt++) {
                int n = br + nt * 8;
                bh[nt][0] = lds32(&sBh[n * SROW + ac]);
                bh[nt][1] = lds32(&sBh[n * SROW + ac + 8]);
                bl[nt][0] = lds32(&sBl[n * SROW + ac]);
                bl[nt][1] = lds32(&sBl[n * SROW + ac + 8]);
            }
#pragma unroll
            for (int mt = 0; mt < 4; mt++)
#pragma unroll
                for (int nt = 0; nt < 4; nt++) {
                    mma_bf16(acc[mt][nt], ah[mt], bh[nt]);
                    mma_bf16(acc[mt][nt], ah[mt], bl[nt]);
                    mma_bf16(acc[mt][nt], al[mt], bh[nt]);
                }
        }
        __syncthreads();
    }

    // epilogue
#pragma unroll
    for (int mt = 0; mt < 4; mt++) {
#pragma unroll
        for (int nt = 0; nt < 4; nt++) {
            int r0 = bm + wm * 64 + mt * 16 + (lane >> 2);
            int c0 = bn + wn * 32 + nt * 8 + (lane & 3) * 2;
#pragma unroll
            for (int q = 0; q < 4; q++) {
                int row = r0 + (q >> 1) * 8;
                int col = c0 + (q & 1);
                float v = acc[mt][nt][q];
                if (bias) v += bias[col];
                size_t o = (size_t)row * HH + col;
                Cf[o] = v;
                if (Chi) {
                    __nv_bfloat16 hb = __float2bfloat16(v);
                    Chi[o] = hb;
                    Clo[o] = __float2bfloat16(v - __bfloat162float(hb));
                }
                if (Cb) Cb[o] = __float2bfloat16(v);
            }
        }
    }
}

// ---------------- fp32 -> bf16 hi/lo split kernels ------------------------
__global__ void split_x_kernel(const float* __restrict__ x) {
    int i = blockIdx.x * blockDim.x + threadIdx.x;
    if (i >= NN * D_IN) return;
    float v = x[i];
    __nv_bfloat16 hb = __float2bfloat16(v);
    g_Ah[i] = hb;
    g_Al[i] = __float2bfloat16(v - __bfloat162float(hb));
}
__global__ void split_w_kernel(const float* __restrict__ W_in,
                               const float* __restrict__ W_gat) {
    int i = blockIdx.x * blockDim.x + threadIdx.x;
    const int NW = D_IN * HH + NL * HH * HH;
    if (i >= NW) return;
    float v = (i < D_IN * HH) ? W_in[i] : W_gat[i - D_IN * HH];
    __nv_bfloat16 hb = __float2bfloat16(v);
    g_Bh[i] = hb;
    g_Bl[i] = __float2bfloat16(v - __bfloat162float(hb));
}

// ---------------- CSR build ----------------------------------------------
__global__ void zero_deg_kernel() {
    int i = blockIdx.x * blockDim.x + threadIdx.x;
    if (i < NN) g_deg[i] = 0;
}
__global__ void csr_hist_kernel(const int* __restrict__ ei) {
    for (int k = blockIdx.x * blockDim.x + threadIdx.x; k < EE;
         k += gridDim.x * blockDim.x)
        atomicAdd(&g_deg[ei[k]], 1);
}
__global__ void csr_scan_kernel() {
    __shared__ int wsum[32];
    int t = threadIdx.x;
    int lane = t & 31, warp = t >> 5;
    int base = t * 8;
    int loc[8];
    int s = 0;
#pragma unroll
    for (int j = 0; j < 8; j++) { loc[j] = s; s += g_deg[base + j]; }
    int v = s;
#pragma unroll
    for (int o = 1; o < 32; o <<= 1) {
        int u = __shfl_up_sync(0xffffffffu, v, o);
        if (lane >= o) v += u;
    }
    if (lane == 31) wsum[warp] = v;
    __syncthreads();
    if (warp == 0) {
        int w = wsum[lane];
#pragma unroll
        for (int o = 1; o < 32; o <<= 1) {
            int u = __shfl_up_sync(0xffffffffu, w, o);
            if (lane >= o) w += u;
        }
        wsum[lane] = w;
    }
    __syncthreads();
    int pre = v - s + (warp ? wsum[warp - 1] : 0);
#pragma unroll
    for (int j = 0; j < 8; j++) {
        g_off[base + j] = pre + loc[j];
        g_cur[base + j] = pre + loc[j];
    }
    if (t == 1023) g_off[NN] = wsum[31];
}
__global__ void csr_scatter_kernel(const int* __restrict__ ei) {
    const int* src = ei;
    const int* tgt = ei + EE;
    for (int k = blockIdx.x * blockDim.x + threadIdx.x; k < EE;
         k += gridDim.x * blockDim.x) {
        int pos = atomicAdd(&g_cur[src[k]], 1);
        g_csr[pos] = tgt[k];
    }
}
__global__ void csr_sort_kernel() {
    int i = blockIdx.x;
    int beg = g_off[i], end = g_off[i + 1];
    int deg = end - beg;
    if (deg <= 1 || deg > 1024) return;
    __shared__ int buf[1024];
    for (int j = threadIdx.x; j < deg; j += blockDim.x) buf[j] = g_csr[beg + j];
    __syncthreads();
    for (int p = 0; p < deg; p++) {
        int start = p & 1;
        for (int j = threadIdx.x; 2 * j + start + 1 < deg; j += blockDim.x) {
            int a = buf[2 * j + start], b = buf[2 * j + start + 1];
            if (a > b) { buf[2 * j + start] = b; buf[2 * j + start + 1] = a; }
        }
        __syncthreads();
    }
    for (int j = threadIdx.x; j < deg; j += blockDim.x) g_csr[beg + j] = buf[j];
}

// ---------------- per-node attention scores ------------------------------
__global__ void scores_kernel(const float* __restrict__ a) {
    int gid  = blockIdx.x * blockDim.x + threadIdx.x;
    int node = gid >> 5;
    int lane = gid & 31;
    if (node >= NN) return;
    const float* row = g_hw + (size_t)node * HH;
    float s1 = 0.f, s2 = 0.f;
    for (int j = lane; j < HH; j += 32) {
        float v = row[j];
        s1 += v * a[j];
        s2 += v * a[HH + j];
    }
#pragma unroll
    for (int o = 16; o; o >>= 1) {
        s1 += __shfl_xor_sync(0xffffffffu, s1, o);
        s2 += __shfl_xor_sync(0xffffffffu, s2, o);
    }
    if (lane == 0) { g_s_src[node] = s1; g_s_tgt[node] = s2; }
}

// ---------------- column sum of hw ---------------------------------------
__global__ void colsum1_kernel() {
    int b = blockIdx.x;
    int c = threadIdx.x;
    int r0 = b * (NN / 64);
    float s = 0.f;
    for (int r = 0; r < NN / 64; r++) s += g_hw[(size_t)(r0 + r) * HH + c];
    g_colsum_part[b * HH + c] = s;
}
__global__ void colsum2_kernel() {
    int c = threadIdx.x;
    float s = 0.f;
    for (int b = 0; b < 64; b++) s += g_colsum_part[b * HH + c];
    g_colsum[c] = s;
}

// ---------------- sparse aggregate + residual + LN + ELU -----------------
__device__ __forceinline__ float4 unp_bf4(uint2 u) {
    __nv_bfloat162 a = *reinterpret_cast<__nv_bfloat162*>(&u.x);
    __nv_bfloat162 b = *reinterpret_cast<__nv_bfloat162*>(&u.y);
    float2 fa = __bfloat1622float2(a), fb = __bfloat1622float2(b);
    return make_float4(fa.x, fa.y, fb.x, fb.y);
}

__global__ void aggregate_kernel(float* __restrict__ h,
                                 const float* __restrict__ lng,
                                 const float* __restrict__ lnb) {
    int i = blockIdx.x;
    int t = threadIdx.x;      // 64, each owns 4 channels
    __shared__ int   st[64];
    __shared__ float sw[64];
    __shared__ float red[64];

    int beg = g_off[i], end = g_off[i + 1];
    float si = g_s_src[i];
    float4 acc = make_float4(0.f, 0.f, 0.f, 0.f);
    float wsum_all = 0.f;

    for (int base = beg; base < end; base += 64) {
        int len = min(64, end - base);
        float w = 0.f;
        if (t < len) {
            int tg = g_csr[base + t];
            st[t] = tg;
            float e = si + g_s_tgt[tg];
            e = (e > 0.f) ? e : 0.2f * e;
            w = expf(e) - 1.f;
            sw[t] = w;
        }
        __syncthreads();
        int k = 0;
        for (; k + 3 < len; k += 4) {
            uint2 u0 = *((const uint2*)(g_hwb + (size_t)st[k] * HH) + t);
            uint2 u1 = *((const uint2*)(g_hwb + (size_t)st[k + 1] * HH) + t);
            uint2 u2 = *((const uint2*)(g_hwb + (size_t)st[k + 2] * HH) + t);
            uint2 u3 = *((const uint2*)(g_hwb + (size_t)st[k + 3] * HH) + t);
            float4 v0 = unp_bf4(u0), v1 = unp_bf4(u1), v2 = unp_bf4(u2), v3 = unp_bf4(u3);
            float w0 = sw[k], w1 = sw[k + 1], w2 = sw[k + 2], w3 = sw[k + 3];
            acc.x = fmaf(w0, v0.x, acc.x); acc.y = fmaf(w0, v0.y, acc.y);
            acc.z = fmaf(w0, v0.z, acc.z); acc.w = fmaf(w0, v0.w, acc.w);
            acc.x = fmaf(w1, v1.x, acc.x); acc.y = fmaf(w1, v1.y, acc.y);
            acc.z = fmaf(w1, v1.z, acc.z); acc.w = fmaf(w1, v1.w, acc.w);
            acc.x = fmaf(w2, v2.x, acc.x); acc.y = fmaf(w2, v2.y, acc.y);
            acc.z = fmaf(w2, v2.z, acc.z); acc.w = fmaf(w2, v2.w, acc.w);
            acc.x = fmaf(w3, v3.x, acc.x); acc.y = fmaf(w3, v3.y, acc.y);
            acc.z = fmaf(w3, v3.z, acc.z); acc.w = fmaf(w3, v3.w, acc.w);
        }
        for (; k < len; k++) {
            float4 v = unp_bf4(*((const uint2*)(g_hwb + (size_t)st[k] * HH) + t));
            float wk = sw[k];
            acc.x = fmaf(wk, v.x, acc.x); acc.y = fmaf(wk, v.y, acc.y);
            acc.z = fmaf(wk, v.z, acc.z); acc.w = fmaf(wk, v.w, acc.w);
        }
        red[t] = w;
        __syncthreads();
#pragma unroll
        for (int o = 32; o > 0; o >>= 1) {
            if (t < o) red[t] += red[t + o];
            __syncthreads();
        }
        wsum_all += red[0];
        __syncthreads();
    }
    float denom = (float)NN + wsum_all;

    float4 cs = *((const float4*)g_colsum + t);
    float4 hv = *((const float4*)(h + (size_t)i * HH) + t);
    float4 v;
    v.x = hv.x + (cs.x + acc.x) / denom;
    v.y = hv.y + (cs.y + acc.y) / denom;
    v.z = hv.z + (cs.z + acc.z) / denom;
    v.w = hv.w + (cs.w + acc.w) / denom;

    red[t] = v.x + v.y + v.z + v.w;
    __syncthreads();
#pragma unroll
    for (int o = 32; o > 0; o >>= 1) {
        if (t < o) red[t] += red[t + o];
        __syncthreads();
    }
    float mu = red[0] / (float)HH;
    __syncthreads();
    float dx = v.x - mu, dy = v.y - mu, dz = v.z - mu, dw = v.w - mu;
    red[t] = dx * dx + dy * dy + dz * dz + dw * dw;
    __syncthreads();
#pragma unroll
    for (int o = 32; o > 0; o >>= 1) {
        if (t < o) red[t] += red[t + o];
        __syncthreads();
    }
    float rs = rsqrtf(red[0] / (float)HH + LN_EPS);
    float4 g = *((const float4*)lng + t);
    float4 b = *((const float4*)lnb + t);
    float4 y;
    y.x = dx * rs * g.x + b.x;
    y.y = dy * rs * g.y + b.y;
    y.z = dz * rs * g.z + b.z;
    y.w = dw * rs * g.w + b.w;
    y.x = (y.x > 0.f) ? y.x : (expf(y.x) - 1.f);
    y.y = (y.y > 0.f) ? y.y : (expf(y.y) - 1.f);
    y.z = (y.z > 0.f) ? y.z : (expf(y.z) - 1.f);
    y.w = (y.w > 0.f) ? y.w : (expf(y.w) - 1.f);
    *((float4*)(h + (size_t)i * HH) + t) = y;

    // emit hi/lo split for next GEMM's A
    size_t o4 = (size_t)i * HH + 4 * t;
#pragma unroll
    for (int q = 0; q < 4; q++) {
        float yy = (q == 0) ? y.x : (q == 1) ? y.y : (q == 2) ? y.z : y.w;
        __nv_bfloat16 hb = __float2bfloat16(yy);
        g_Ah2[o4 + q] = hb;
        g_Al2[o4 + q] = __float2bfloat16(yy - __bfloat162float(hb));
    }
}

// ---------------- gated pooling ------------------------------------------
__global__ void pool1_kernel(const float* __restrict__ h,
                             const float* __restrict__ Wp,
                             const float* __restrict__ bp) {
    __shared__ float gates[128];
    int b = blockIdx.x;
    int t = threadIdx.x;
    int warp = t >> 5, lane = t & 31;
    int base = b * 128;
    for (int it = 0; it < 16; it++) {
        int n = base + warp * 16 + it;
        const float* row = h + (size_t)n * HH;
        float s = 0.f;
        for (int j = lane; j < HH; j += 32) s += row[j] * Wp[j];
#pragma unroll
        for (int o = 16; o; o >>= 1) s += __shfl_xor_sync(0xffffffffu, s, o);
        if (lane == 0) gates[warp * 16 + it] = 1.f / (1.f + expf(-(s + bp[0])));
    }
    __syncthreads();
    int c = t;
    float s = 0.f;
    for (int ln = 0; ln < 128; ln++)
        s = fmaf(gates[ln], h[(size_t)(base + ln) * HH + c], s);
    g_pool_part[b * HH + c] = s;
}
__global__ void pool2_kernel(float* __restrict__ emb) {
    int c = threadIdx.x;
    float s = 0.f;
    for (int b = 0; b < 64; b++) s += g_pool_part[b * HH + c];
    emb[c] = s;
}

// ---------------- launch --------------------------------------------------
extern "C" void kernel_launch(void* const* d_in, const int* in_sizes, int n_in,
                              void* d_out, int out_size) {
    const float* x      = (const float*)d_in[0];
    const int*   ei     = (const int*)d_in[1];
    const float* W_in   = (const float*)d_in[2];
    const float* b_in   = (const float*)d_in[3];
    const float* W_gat  = (const float*)d_in[4];
    const float* a_gat  = (const float*)d_in[5];
    const float* ln_g   = (const float*)d_in[6];
    const float* ln_b   = (const float*)d_in[7];
    const float* W_pool = (const float*)d_in[8];
    const float* b_pool = (const float*)d_in[9];

    float* out = (float*)d_out;
    float* h   = out;

    float* hw_ptr = nullptr;
    cudaGetSymbolAddress((void**)&hw_ptr, g_hw);
    __nv_bfloat16 *Ah, *Al, *Ah2, *Al2, *Bh, *Bl, *hwb;
    cudaGetSymbolAddress((void**)&Ah,  g_Ah);
    cudaGetSymbolAddress((void**)&Al,  g_Al);
    cudaGetSymbolAddress((void**)&Ah2, g_Ah2);
    cudaGetSymbolAddress((void**)&Al2, g_Al2);
    cudaGetSymbolAddress((void**)&Bh,  g_Bh);
    cudaGetSymbolAddress((void**)&Bl,  g_Bl);
    cudaGetSymbolAddress((void**)&hwb, g_hwb);

    zero_deg_kernel<<<NN / 256, 256>>>();
    split_x_kernel<<<(NN * D_IN + 255) / 256, 256>>>(x);
    split_w_kernel<<<(D_IN * HH + NL * HH * HH + 255) / 256, 256>>>(W_in, W_gat);

    csr_hist_kernel<<<256, 256>>>(ei);
    csr_scan_kernel<<<1, 1024>>>();
    csr_scatter_kernel<<<256, 256>>>(ei);
    csr_sort_kernel<<<NN, 128>>>();

    // h = x @ W_in^T + b_in; emit h split for layer GEMMs
    gemm_mma<<<dim3(64, 2), 256>>>(Ah, Al, Bh, Bl, b_in, h, Ah2, Al2,
                                   (__nv_bfloat16*)nullptr, D_IN);

    for (int l = 0; l < NL; l++) {
        const __nv_bfloat16* Wh = Bh + D_IN * HH + (size_t)l * HH * HH;
        const __nv_bfloat16* Wl = Bl + D_IN * HH + (size_t)l * HH * HH;
        gemm_mma<<<dim3(64, 2), 256>>>(Ah2, Al2, Wh, Wl, nullptr, hw_ptr,
                                       (__nv_bfloat16*)nullptr,
                                       (__nv_bfloat16*)nullptr, hwb, HH);
        scores_kernel<<<NN / 8, 256>>>(a_gat + (size_t)l * 2 * HH);
        colsum1_kernel<<<64, 256>>>();
        colsum2_kernel<<<1, 256>>>();
        aggregate_kernel<<<NN, 64>>>(h, ln_g + (size_t)l * HH, ln_b + (size_t)l * HH);
    }

    pool1_kernel<<<64, 256>>>(h, W_pool, b_pool);
    pool2_kernel<<<1, 256>>>(out + (size_t)NN * HH);
}

// round 8
// speedup vs baseline: 2.3227x; 1.1031x over previous
#include <cuda_runtime.h>
#include <cuda_bf16.h>
#include <math.h>
#include <stdint.h>

// Problem constants
#define NN    8192
#define D_IN  512
#define HH    256
#define EE    262144
#define NL    2
#define LN_EPS 1e-5f

// ---------------- device scratch (no allocations allowed) ----------------
__device__ __nv_bfloat16 g_hwb[NN * HH];        // hw bf16 for gathers
__device__ __nv_bfloat16 g_Ah[NN * D_IN];       // x split hi
__device__ __nv_bfloat16 g_Al[NN * D_IN];       // x split lo
__device__ __nv_bfloat16 g_Ah2[NN * HH];        // h split hi
__device__ __nv_bfloat16 g_Al2[NN * HH];        // h split lo
__device__ __nv_bfloat16 g_Bh[D_IN * HH + NL * HH * HH];  // weights hi
__device__ __nv_bfloat16 g_Bl[D_IN * HH + NL * HH * HH];  // weights lo
__device__ float g_s_srcp[2 * NN];              // score partials (per N-half)
__device__ float g_s_tgtp[2 * NN];
__device__ int   g_deg[NN];
__device__ int   g_off[NN + 1];
__device__ int   g_cur[NN];
__device__ int   g_csr[EE];
__device__ float g_colsum_part[64 * HH];        // per M-CTA column partials
__device__ float g_colsum[HH];
__device__ float g_pool_part[64 * HH];

// ---------------- HMMA GEMM: C[8192 x 256] = A * B^T ---------------------
// Block 128x128, 8 warps (2x4), warp tile 64x32. bf16 split inputs,
// 3 accumulating passes, fp32 accum. Register-prefetch double buffering.
// Epilogue optionally computes attention score partials + column-sum partials.
#define SROW 40     // smem row stride in bf16 (conflict-free fragment loads)

__device__ __forceinline__ uint32_t lds32(const __nv_bfloat16* p) {
    return *(const uint32_t*)p;
}
__device__ __forceinline__ void mma_bf16(float* d, const uint32_t* a, const uint32_t* b) {
    asm volatile(
        "mma.sync.aligned.m16n8k16.row.col.f32.bf16.bf16.f32 "
        "{%0,%1,%2,%3}, {%4,%5,%6,%7}, {%8,%9}, {%0,%1,%2,%3};"
        : "+f"(d[0]), "+f"(d[1]), "+f"(d[2]), "+f"(d[3])
        : "r"(a[0]), "r"(a[1]), "r"(a[2]), "r"(a[3]), "r"(b[0]), "r"(b[1]));
}

__global__ __launch_bounds__(256)
void gemm_mma(const __nv_bfloat16* __restrict__ Ah, const __nv_bfloat16* __restrict__ Al,
              const __nv_bfloat16* __restrict__ Bh, const __nv_bfloat16* __restrict__ Bl,
              const float* __restrict__ bias, float* __restrict__ Cf,
              __nv_bfloat16* __restrict__ Chi, __nv_bfloat16* __restrict__ Clo,
              __nv_bfloat16* __restrict__ Cb,
              const float* __restrict__ a_att,   // non-null => attn epilogue
              int K) {
    __shared__ __nv_bfloat16 sAh[128 * SROW];
    __shared__ __nv_bfloat16 sAl[128 * SROW];
    __shared__ __nv_bfloat16 sBh[128 * SROW];
    __shared__ __nv_bfloat16 sBl[128 * SROW];
    int tid = threadIdx.x;
    int wid = tid >> 5, lane = tid & 31;
    int wm = wid >> 2, wn = wid & 3;
    int bm = blockIdx.x * 128;
    int bn = blockIdx.y * 128;

    float acc[4][4][4];
#pragma unroll
    for (int mt = 0; mt < 4; mt++)
#pragma unroll
        for (int nt = 0; nt < 4; nt++)
#pragma unroll
            for (int q = 0; q < 4; q++) acc[mt][nt][q] = 0.f;

    const int NCH = K >> 5;

    uint4 pA[2][2], pB[2][2];  // [q][hi/lo]
    // preload chunk 0
#pragma unroll
    for (int q = 0; q < 2; q++) {
        int idx = tid + q * 256;
        int r = idx >> 2, u = idx & 3;
        size_t ga = (size_t)(bm + r) * K + u * 8;
        size_t gb = (size_t)(bn + r) * K + u * 8;
        pA[q][0] = *(const uint4*)(Ah + ga);
        pA[q][1] = *(const uint4*)(Al + ga);
        pB[q][0] = *(const uint4*)(Bh + gb);
        pB[q][1] = *(const uint4*)(Bl + gb);
    }
#pragma unroll
    for (int q = 0; q < 2; q++) {
        int idx = tid + q * 256;
        int r = idx >> 2, u = idx & 3;
        int so = r * SROW + u * 8;
        *(uint4*)&sAh[so] = pA[q][0];
        *(uint4*)&sAl[so] = pA[q][1];
        *(uint4*)&sBh[so] = pB[q][0];
        *(uint4*)&sBl[so] = pB[q][1];
    }
    __syncthreads();

    for (int kc = 0; kc < NCH; kc++) {
        bool has = (kc + 1) < NCH;
        if (has) {
            int k0 = (kc + 1) * 32;
#pragma unroll
            for (int q = 0; q < 2; q++) {
                int idx = tid + q * 256;
                int r = idx >> 2, u = idx & 3;
                size_t ga = (size_t)(bm + r) * K + k0 + u * 8;
                size_t gb = (size_t)(bn + r) * K + k0 + u * 8;
                pA[q][0] = *(const uint4*)(Ah + ga);
                pA[q][1] = *(const uint4*)(Al + ga);
                pB[q][0] = *(const uint4*)(Bh + gb);
                pB[q][1] = *(const uint4*)(Bl + gb);
            }
        }
#pragma unroll
        for (int ks = 0; ks < 2; ks++) {
            int ar = wm * 64 + (lane >> 2);
            int ac = ks * 16 + (lane & 3) * 2;
            uint32_t ah[4][4], al[4][4], bh[4][2], bl[4][2];
#pragma unroll
            for (int mt = 0; mt < 4; mt++) {
                int r = ar + mt * 16;
                ah[mt][0] = lds32(&sAh[r * SROW + ac]);
                ah[mt][1] = lds32(&sAh[(r + 8) * SROW + ac]);
                ah[mt][2] = lds32(&sAh[r * SROW + ac + 8]);
                ah[mt][3] = lds32(&sAh[(r + 8) * SROW + ac + 8]);
                al[mt][0] = lds32(&sAl[r * SROW + ac]);
                al[mt][1] = lds32(&sAl[(r + 8) * SROW + ac]);
                al[mt][2] = lds32(&sAl[r * SROW + ac + 8]);
                al[mt][3] = lds32(&sAl[(r + 8) * SROW + ac + 8]);
            }
            int br = wn * 32 + (lane >> 2);
#pragma unroll
            for (int nt = 0; nt < 4; nt++) {
                int n = br + nt * 8;
                bh[nt][0] = lds32(&sBh[n * SROW + ac]);
                bh[nt][1] = lds32(&sBh[n * SROW + ac + 8]);
                bl[nt][0] = lds32(&sBl[n * SROW + ac]);
                bl[nt][1] = lds32(&sBl[n * SROW + ac + 8]);
            }
#pragma unroll
            for (int mt = 0; mt < 4; mt++)
#pragma unroll
                for (int nt = 0; nt < 4; nt++) {
                    mma_bf16(acc[mt][nt], ah[mt], bh[nt]);
                    mma_bf16(acc[mt][nt], ah[mt], bl[nt]);
                    mma_bf16(acc[mt][nt], al[mt], bh[nt]);
                }
        }
        __syncthreads();
        if (has) {
#pragma unroll
            for (int q = 0; q < 2; q++) {
                int idx = tid + q * 256;
                int r = idx >> 2, u = idx & 3;
                int so = r * SROW + u * 8;
                *(uint4*)&sAh[so] = pA[q][0];
                *(uint4*)&sAl[so] = pA[q][1];
                *(uint4*)&sBh[so] = pB[q][0];
                *(uint4*)&sBl[so] = pB[q][1];
            }
            __syncthreads();
        }
    }

    // ---- main output stores ----
#pragma unroll
    for (int mt = 0; mt < 4; mt++) {
#pragma unroll
        for (int nt = 0; nt < 4; nt++) {
            int r0 = bm + wm * 64 + mt * 16 + (lane >> 2);
            int c0 = bn + wn * 32 + nt * 8 + (lane & 3) * 2;
#pragma unroll
            for (int q = 0; q < 4; q++) {
                int row = r0 + (q >> 1) * 8;
                int col = c0 + (q & 1);
                float v = acc[mt][nt][q];
                if (bias) { v += bias[col]; acc[mt][nt][q] = v; }
                size_t o = (size_t)row * HH + col;
                if (Cf) Cf[o] = v;
                if (Chi) {
                    __nv_bfloat16 hb = __float2bfloat16(v);
                    Chi[o] = hb;
                    Clo[o] = __float2bfloat16(v - __bfloat162float(hb));
                }
                if (Cb) Cb[o] = __float2bfloat16(v);
            }
        }
    }

    // ---- fused attention-prep epilogue (layer GEMMs only) ----
    if (a_att) {
        // column partials (sum over this warp's 64 rows)
        float colp[8];
#pragma unroll
        for (int j = 0; j < 8; j++) colp[j] = 0.f;
#pragma unroll
        for (int mt = 0; mt < 4; mt++)
#pragma unroll
            for (int nt = 0; nt < 4; nt++)
#pragma unroll
                for (int q = 0; q < 4; q++)
                    colp[nt * 2 + (q & 1)] += acc[mt][nt][q];
#pragma unroll
        for (int off = 4; off <= 16; off <<= 1)
#pragma unroll
            for (int j = 0; j < 8; j++)
                colp[j] += __shfl_xor_sync(0xffffffffu, colp[j], off);

        // score row partials (dot over this warp's 32 cols)
        float a_s[8], a_t[8];
#pragma unroll
        for (int nt = 0; nt < 4; nt++)
#pragma unroll
            for (int qb = 0; qb < 2; qb++) {
                int col = bn + wn * 32 + nt * 8 + (lane & 3) * 2 + qb;
                a_s[nt * 2 + qb] = __ldg(a_att + col);
                a_t[nt * 2 + qb] = __ldg(a_att + HH + col);
            }
        float rs_[8], rt_[8];
#pragma unroll
        for (int j = 0; j < 8; j++) { rs_[j] = 0.f; rt_[j] = 0.f; }
#pragma unroll
        for (int mt = 0; mt < 4; mt++)
#pragma unroll
            for (int nt = 0; nt < 4; nt++)
#pragma unroll
                for (int q = 0; q < 4; q++) {
                    float v = acc[mt][nt][q];
                    rs_[mt * 2 + (q >> 1)] += v * a_s[nt * 2 + (q & 1)];
                    rt_[mt * 2 + (q >> 1)] += v * a_t[nt * 2 + (q & 1)];
                }
#pragma unroll
        for (int off = 1; off <= 2; off <<= 1)
#pragma unroll
            for (int j = 0; j < 8; j++) {
                rs_[j] += __shfl_xor_sync(0xffffffffu, rs_[j], off);
                rt_[j] += __shfl_xor_sync(0xffffffffu, rt_[j], off);
            }

        // stage in dead smem: sS[4][128], sT[4][128], sC[8][32]
        float* sS = (float*)sAh;
        float* sT = sS + 512;
        float* sC = sT + 512;
        if ((lane & 3) == 0) {
#pragma unroll
            for (int mt = 0; mt < 4; mt++)
#pragma unroll
                for (int rq = 0; rq < 2; rq++) {
                    int row = wm * 64 + mt * 16 + rq * 8 + (lane >> 2);
                    sS[wn * 128 + row] = rs_[mt * 2 + rq];
                    sT[wn * 128 + row] = rt_[mt * 2 + rq];
                }
        }
        if (lane < 4) {
#pragma unroll
            for (int nt = 0; nt < 4; nt++)
#pragma unroll
                for (int qb = 0; qb < 2; qb++)
                    sC[wid * 32 + nt * 8 + (lane & 3) * 2 + qb] = colp[nt * 2 + qb];
        }
        __syncthreads();
        if (tid < 128) {
            float ss = sS[tid] + sS[128 + tid] + sS[256 + tid] + sS[384 + tid];
            float tt = sT[tid] + sT[128 + tid] + sT[256 + tid] + sT[384 + tid];
            g_s_srcp[blockIdx.y * NN + bm + tid] = ss;
            g_s_tgtp[blockIdx.y * NN + bm + tid] = tt;
            int wnc = tid >> 5, ci = tid & 31;
            float cv = sC[wnc * 32 + ci] + sC[(4 + wnc) * 32 + ci];
            g_colsum_part[blockIdx.x * HH + bn + tid] = cv;
        }
    }
}

// ---------------- fp32 -> bf16 hi/lo split kernels ------------------------
__global__ void split_x_kernel(const float* __restrict__ x) {
    int i = blockIdx.x * blockDim.x + threadIdx.x;
    if (i >= NN * D_IN) return;
    float v = x[i];
    __nv_bfloat16 hb = __float2bfloat16(v);
    g_Ah[i] = hb;
    g_Al[i] = __float2bfloat16(v - __bfloat162float(hb));
}
__global__ void split_w_kernel(const float* __restrict__ W_in,
                               const float* __restrict__ W_gat) {
    int i = blockIdx.x * blockDim.x + threadIdx.x;
    const int NW = D_IN * HH + NL * HH * HH;
    if (i >= NW) return;
    float v = (i < D_IN * HH) ? W_in[i] : W_gat[i - D_IN * HH];
    __nv_bfloat16 hb = __float2bfloat16(v);
    g_Bh[i] = hb;
    g_Bl[i] = __float2bfloat16(v - __bfloat162float(hb));
}

// ---------------- CSR build ----------------------------------------------
__global__ void zero_deg_kernel() {
    int i = blockIdx.x * blockDim.x + threadIdx.x;
    if (i < NN) g_deg[i] = 0;
}
__global__ void csr_hist_kernel(const int* __restrict__ ei) {
    for (int k = blockIdx.x * blockDim.x + threadIdx.x; k < EE;
         k += gridDim.x * blockDim.x)
        atomicAdd(&g_deg[ei[k]], 1);
}
__global__ void csr_scan_kernel() {
    __shared__ int wsum[32];
    int t = threadIdx.x;
    int lane = t & 31, warp = t >> 5;
    int base = t * 8;
    int loc[8];
    int s = 0;
#pragma unroll
    for (int j = 0; j < 8; j++) { loc[j] = s; s += g_deg[base + j]; }
    int v = s;
#pragma unroll
    for (int o = 1; o < 32; o <<= 1) {
        int u = __shfl_up_sync(0xffffffffu, v, o);
        if (lane >= o) v += u;
    }
    if (lane == 31) wsum[warp] = v;
    __syncthreads();
    if (warp == 0) {
        int w = wsum[lane];
#pragma unroll
        for (int o = 1; o < 32; o <<= 1) {
            int u = __shfl_up_sync(0xffffffffu, w, o);
            if (lane >= o) w += u;
        }
        wsum[lane] = w;
    }
    __syncthreads();
    int pre = v - s + (warp ? wsum[warp - 1] : 0);
#pragma unroll
    for (int j = 0; j < 8; j++) {
        g_off[base + j] = pre + loc[j];
        g_cur[base + j] = pre + loc[j];
    }
    if (t == 1023) g_off[NN] = wsum[31];
}
__global__ void csr_scatter_kernel(const int* __restrict__ ei) {
    const int* src = ei;
    const int* tgt = ei + EE;
    for (int k = blockIdx.x * blockDim.x + threadIdx.x; k < EE;
         k += gridDim.x * blockDim.x) {
        int pos = atomicAdd(&g_cur[src[k]], 1);
        g_csr[pos] = tgt[k];
    }
}
__global__ void csr_sort_kernel() {
    int i = blockIdx.x;
    int beg = g_off[i], end = g_off[i + 1];
    int deg = end - beg;
    if (deg <= 1 || deg > 1024) return;
    __shared__ int buf[1024];
    for (int j = threadIdx.x; j < deg; j += blockDim.x) buf[j] = g_csr[beg + j];
    __syncthreads();
    for (int p = 0; p < deg; p++) {
        int start = p & 1;
        for (int j = threadIdx.x; 2 * j + start + 1 < deg; j += blockDim.x) {
            int a = buf[2 * j + start], b = buf[2 * j + start + 1];
            if (a > b) { buf[2 * j + start] = b; buf[2 * j + start + 1] = a; }
        }
        __syncthreads();
    }
    for (int j = threadIdx.x; j < deg; j += blockDim.x) g_csr[beg + j] = buf[j];
}

// ---------------- colsum finalize -----------------------------------------
__global__ void colsum2_kernel() {
    int c = threadIdx.x;
    float s = 0.f;
    for (int b = 0; b < 64; b++) s += g_colsum_part[b * HH + c];
    g_colsum[c] = s;
}

// ---------------- warp-per-node aggregate + residual + LN + ELU ----------
__device__ __forceinline__ float4 unp_bf4u(uint32_t lo, uint32_t hi) {
    __nv_bfloat162 a = *reinterpret_cast<__nv_bfloat162*>(&lo);
    __nv_bfloat162 b = *reinterpret_cast<__nv_bfloat162*>(&hi);
    float2 fa = __bfloat1622float2(a), fb = __bfloat1622float2(b);
    return make_float4(fa.x, fa.y, fb.x, fb.y);
}

__global__ __launch_bounds__(256)
void aggregate_kernel(float* __restrict__ h,
                      const float* __restrict__ lng,
                      const float* __restrict__ lnb) {
    int wid = threadIdx.x >> 5, lane = threadIdx.x & 31;
    int i = blockIdx.x * 8 + wid;
    int beg = g_off[i], end = g_off[i + 1];
    float si = g_s_srcp[i] + g_s_srcp[NN + i];

    float4 a0 = make_float4(0.f, 0.f, 0.f, 0.f);
    float4 a1 = make_float4(0.f, 0.f, 0.f, 0.f);
    float wsum = 0.f;

    for (int base = beg; base < end; base += 32) {
        int idx = base + lane;
        int tg = 0;
        float w = 0.f;
        if (idx < end) {
            tg = g_csr[idx];
            float e = si + g_s_tgtp[tg] + g_s_tgtp[NN + tg];
            e = (e > 0.f) ? e : 0.2f * e;
            w = expf(e) - 1.f;
        }
        float wr = w;
#pragma unroll
        for (int o = 16; o; o >>= 1) wr += __shfl_xor_sync(0xffffffffu, wr, o);
        wsum += wr;
        int len = min(32, end - base);
        for (int k = 0; k < len; k++) {
            float wk = __shfl_sync(0xffffffffu, w, k);
            int   tk = __shfl_sync(0xffffffffu, tg, k);
            uint4 u = *((const uint4*)(g_hwb + (size_t)tk * HH) + lane);
            float4 v0 = unp_bf4u(u.x, u.y);
            float4 v1 = unp_bf4u(u.z, u.w);
            a0.x = fmaf(wk, v0.x, a0.x); a0.y = fmaf(wk, v0.y, a0.y);
            a0.z = fmaf(wk, v0.z, a0.z); a0.w = fmaf(wk, v0.w, a0.w);
            a1.x = fmaf(wk, v1.x, a1.x); a1.y = fmaf(wk, v1.y, a1.y);
            a1.z = fmaf(wk, v1.z, a1.z); a1.w = fmaf(wk, v1.w, a1.w);
        }
    }
    float denom = (float)NN + wsum;

    float4 cs0 = *((const float4*)g_colsum + lane * 2);
    float4 cs1 = *((const float4*)g_colsum + lane * 2 + 1);
    float4 h0 = *((const float4*)(h + (size_t)i * HH) + lane * 2);
    float4 h1 = *((const float4*)(h + (size_t)i * HH) + lane * 2 + 1);
    float4 v0, v1;
    v0.x = h0.x + (cs0.x + a0.x) / denom;
    v0.y = h0.y + (cs0.y + a0.y) / denom;
    v0.z = h0.z + (cs0.z + a0.z) / denom;
    v0.w = h0.w + (cs0.w + a0.w) / denom;
    v1.x = h1.x + (cs1.x + a1.x) / denom;
    v1.y = h1.y + (cs1.y + a1.y) / denom;
    v1.z = h1.z + (cs1.z + a1.z) / denom;
    v1.w = h1.w + (cs1.w + a1.w) / denom;

    float ts = v0.x + v0.y + v0.z + v0.w + v1.x + v1.y + v1.z + v1.w;
#pragma unroll
    for (int o = 16; o; o >>= 1) ts += __shfl_xor_sync(0xffffffffu, ts, o);
    float mu = ts / (float)HH;
    float d0x = v0.x - mu, d0y = v0.y - mu, d0z = v0.z - mu, d0w = v0.w - mu;
    float d1x = v1.x - mu, d1y = v1.y - mu, d1z = v1.z - mu, d1w = v1.w - mu;
    float tv = d0x * d0x + d0y * d0y + d0z * d0z + d0w * d0w
             + d1x * d1x + d1y * d1y + d1z * d1z + d1w * d1w;
#pragma unroll
    for (int o = 16; o; o >>= 1) tv += __shfl_xor_sync(0xffffffffu, tv, o);
    float rs = rsqrtf(tv / (float)HH + LN_EPS);

    float4 g0 = *((const float4*)lng + lane * 2);
    float4 g1 = *((const float4*)lng + lane * 2 + 1);
    float4 b0 = *((const float4*)lnb + lane * 2);
    float4 b1 = *((const float4*)lnb + lane * 2 + 1);
    float y[8];
    y[0] = d0x * rs * g0.x + b0.x; y[1] = d0y * rs * g0.y + b0.y;
    y[2] = d0z * rs * g0.z + b0.z; y[3] = d0w * rs * g0.w + b0.w;
    y[4] = d1x * rs * g1.x + b1.x; y[5] = d1y * rs * g1.y + b1.y;
    y[6] = d1z * rs * g1.z + b1.z; y[7] = d1w * rs * g1.w + b1.w;
#pragma unroll
    for (int j = 0; j < 8; j++) y[j] = (y[j] > 0.f) ? y[j] : (expf(y[j]) - 1.f);

    float4 o0 = make_float4(y[0], y[1], y[2], y[3]);
    float4 o1 = make_float4(y[4], y[5], y[6], y[7]);
    *((float4*)(h + (size_t)i * HH) + lane * 2)     = o0;
    *((float4*)(h + (size_t)i * HH) + lane * 2 + 1) = o1;

    // hi/lo split for next GEMM
    uint32_t hiw[4], low[4];
#pragma unroll
    for (int p = 0; p < 4; p++) {
        __nv_bfloat16 h0b = __float2bfloat16(y[2 * p]);
        __nv_bfloat16 h1b = __float2bfloat16(y[2 * p + 1]);
        float l0 = y[2 * p] - __bfloat162float(h0b);
        float l1 = y[2 * p + 1] - __bfloat162float(h1b);
        __nv_bfloat162 hp = __nv_bfloat162(h0b, h1b);
        __nv_bfloat162 lp = __nv_bfloat162(__float2bfloat16(l0), __float2bfloat16(l1));
        hiw[p] = *reinterpret_cast<uint32_t*>(&hp);
        low[p] = *reinterpret_cast<uint32_t*>(&lp);
    }
    *((uint4*)(g_Ah2 + (size_t)i * HH) + lane) = make_uint4(hiw[0], hiw[1], hiw[2], hiw[3]);
    *((uint4*)(g_Al2 + (size_t)i * HH) + lane) = make_uint4(low[0], low[1], low[2], low[3]);
}

// ---------------- gated pooling ------------------------------------------
__global__ void pool1_kernel(const float* __restrict__ h,
                             const float* __restrict__ Wp,
                             const float* __restrict__ bp) {
    __shared__ float gates[128];
    int b = blockIdx.x;
    int t = threadIdx.x;
    int warp = t >> 5, lane = t & 31;
    int base = b * 128;
    for (int it = 0; it < 16; it++) {
        int n = base + warp * 16 + it;
        const float* row = h + (size_t)n * HH;
        float s = 0.f;
        for (int j = lane; j < HH; j += 32) s += row[j] * Wp[j];
#pragma unroll
        for (int o = 16; o; o >>= 1) s += __shfl_xor_sync(0xffffffffu, s, o);
        if (lane == 0) gates[warp * 16 + it] = 1.f / (1.f + expf(-(s + bp[0])));
    }
    __syncthreads();
    int c = t;
    float s = 0.f;
    for (int ln = 0; ln < 128; ln++)
        s = fmaf(gates[ln], h[(size_t)(base + ln) * HH + c], s);
    g_pool_part[b * HH + c] = s;
}
__global__ void pool2_kernel(float* __restrict__ emb) {
    int c = threadIdx.x;
    float s = 0.f;
    for (int b = 0; b < 64; b++) s += g_pool_part[b * HH + c];
    emb[c] = s;
}

// ---------------- launch --------------------------------------------------
extern "C" void kernel_launch(void* const* d_in, const int* in_sizes, int n_in,
                              void* d_out, int out_size) {
    const float* x      = (const float*)d_in[0];
    const int*   ei     = (const int*)d_in[1];
    const float* W_in   = (const float*)d_in[2];
    const float* b_in   = (const float*)d_in[3];
    const float* W_gat  = (const float*)d_in[4];
    const float* a_gat  = (const float*)d_in[5];
    const float* ln_g   = (const float*)d_in[6];
    const float* ln_b   = (const float*)d_in[7];
    const float* W_pool = (const float*)d_in[8];
    const float* b_pool = (const float*)d_in[9];

    float* out = (float*)d_out;
    float* h   = out;

    __nv_bfloat16 *Ah, *Al, *Ah2, *Al2, *Bh, *Bl, *hwb;
    cudaGetSymbolAddress((void**)&Ah,  g_Ah);
    cudaGetSymbolAddress((void**)&Al,  g_Al);
    cudaGetSymbolAddress((void**)&Ah2, g_Ah2);
    cudaGetSymbolAddress((void**)&Al2, g_Al2);
    cudaGetSymbolAddress((void**)&Bh,  g_Bh);
    cudaGetSymbolAddress((void**)&Bl,  g_Bl);
    cudaGetSymbolAddress((void**)&hwb, g_hwb);

    zero_deg_kernel<<<NN / 256, 256>>>();
    split_x_kernel<<<(NN * D_IN + 255) / 256, 256>>>(x);
    split_w_kernel<<<(D_IN * HH + NL * HH * HH + 255) / 256, 256>>>(W_in, W_gat);

    csr_hist_kernel<<<256, 256>>>(ei);
    csr_scan_kernel<<<1, 1024>>>();
    csr_scatter_kernel<<<256, 256>>>(ei);
    csr_sort_kernel<<<NN, 128>>>();

    // h = x @ W_in^T + b_in; emit h split for layer GEMMs
    gemm_mma<<<dim3(64, 2), 256>>>(Ah, Al, Bh, Bl, b_in, h, Ah2, Al2,
                                   (__nv_bfloat16*)nullptr, nullptr, D_IN);

    for (int l = 0; l < NL; l++) {
        const __nv_bfloat16* Wh = Bh + D_IN * HH + (size_t)l * HH * HH;
        const __nv_bfloat16* Wl = Bl + D_IN * HH + (size_t)l * HH * HH;
        gemm_mma<<<dim3(64, 2), 256>>>(Ah2, Al2, Wh, Wl, nullptr, nullptr,
                                       (__nv_bfloat16*)nullptr,
                                       (__nv_bfloat16*)nullptr, hwb,
                                       a_gat + (size_t)l * 2 * HH, HH);
        colsum2_kernel<<<1, 256>>>();
        aggregate_kernel<<<NN / 8, 256>>>(h, ln_g + (size_t)l * HH,
                                          ln_b + (size_t)l * HH);
    }

    pool1_kernel<<<64, 256>>>(h, W_pool, b_pool);
    pool2_kernel<<<1, 256>>>(out + (size_t)NN * HH);
}

// round 14
// speedup vs baseline: 2.7474x; 1.1829x over previous
#include <cuda_runtime.h>
#include <cuda_bf16.h>
#include <math.h>
#include <stdint.h>

// Problem constants
#define NN    8192
#define D_IN  512
#define HH    256
#define EE    262144
#define NL    2
#define LN_EPS 1e-5f
#define BCAP  128      // per-node bucket capacity (max deg ~60)

// ---------------- device scratch (no allocations allowed) ----------------
__device__ __nv_bfloat16 g_hwb[NN * HH];        // hw bf16 for gathers
__device__ __nv_bfloat16 g_Ah[NN * D_IN];       // x split hi
__device__ __nv_bfloat16 g_Al[NN * D_IN];       // x split lo
__device__ __nv_bfloat16 g_Ah2[NN * HH];        // h split hi
__device__ __nv_bfloat16 g_Al2[NN * HH];        // h split lo
__device__ __nv_bfloat16 g_Bh[D_IN * HH + NL * HH * HH];  // weights hi
__device__ __nv_bfloat16 g_Bl[D_IN * HH + NL * HH * HH];  // weights lo
__device__ float g_s_srcp[2 * NN];              // score partials (per N-half)
__device__ float g_s_tgtp[2 * NN];
__device__ float g_s_src[NN];                   // combined scores
__device__ float g_s_tgt[NN];
__device__ int   g_cnt[NN];
__device__ int   g_bkt[NN * BCAP];              // per-node target buckets
__device__ float g_colsum_part[64 * HH];        // per M-CTA column partials
__device__ float g_colsum[HH];
__device__ float g_pool_part[64 * HH];

// ---------------- HMMA GEMM: C[8192 x 256] = A * B^T ---------------------
// Block 128x128, 8 warps (2x4), warp tile 64x32. bf16 split inputs,
// 3 accumulating passes, fp32 accum. Register-prefetch double buffering.
// Epilogue optionally computes attention score partials + column-sum partials.
#define SROW 40     // smem row stride in bf16 (conflict-free fragment loads)

__device__ __forceinline__ uint32_t lds32(const __nv_bfloat16* p) {
    return *(const uint32_t*)p;
}
__device__ __forceinline__ void mma_bf16(float* d, const uint32_t* a, const uint32_t* b) {
    asm volatile(
        "mma.sync.aligned.m16n8k16.row.col.f32.bf16.bf16.f32 "
        "{%0,%1,%2,%3}, {%4,%5,%6,%7}, {%8,%9}, {%0,%1,%2,%3};"
        : "+f"(d[0]), "+f"(d[1]), "+f"(d[2]), "+f"(d[3])
        : "r"(a[0]), "r"(a[1]), "r"(a[2]), "r"(a[3]), "r"(b[0]), "r"(b[1]));
}

__global__ __launch_bounds__(256)
void gemm_mma(const __nv_bfloat16* __restrict__ Ah, const __nv_bfloat16* __restrict__ Al,
              const __nv_bfloat16* __restrict__ Bh, const __nv_bfloat16* __restrict__ Bl,
              const float* __restrict__ bias, float* __restrict__ Cf,
              __nv_bfloat16* __restrict__ Chi, __nv_bfloat16* __restrict__ Clo,
              __nv_bfloat16* __restrict__ Cb,
              const float* __restrict__ a_att,   // non-null => attn epilogue
              int K) {
    __shared__ __nv_bfloat16 sAh[128 * SROW];
    __shared__ __nv_bfloat16 sAl[128 * SROW];
    __shared__ __nv_bfloat16 sBh[128 * SROW];
    __shared__ __nv_bfloat16 sBl[128 * SROW];
    int tid = threadIdx.x;
    int wid = tid >> 5, lane = tid & 31;
    int wm = wid >> 2, wn = wid & 3;
    int bm = blockIdx.x * 128;
    int bn = blockIdx.y * 128;

    float acc[4][4][4];
#pragma unroll
    for (int mt = 0; mt < 4; mt++)
#pragma unroll
        for (int nt = 0; nt < 4; nt++)
#pragma unroll
            for (int q = 0; q < 4; q++) acc[mt][nt][q] = 0.f;

    const int NCH = K >> 5;

    uint4 pA[2][2], pB[2][2];
#pragma unroll
    for (int q = 0; q < 2; q++) {
        int idx = tid + q * 256;
        int r = idx >> 2, u = idx & 3;
        size_t ga = (size_t)(bm + r) * K + u * 8;
        size_t gb = (size_t)(bn + r) * K + u * 8;
        pA[q][0] = *(const uint4*)(Ah + ga);
        pA[q][1] = *(const uint4*)(Al + ga);
        pB[q][0] = *(const uint4*)(Bh + gb);
        pB[q][1] = *(const uint4*)(Bl + gb);
    }
#pragma unroll
    for (int q = 0; q < 2; q++) {
        int idx = tid + q * 256;
        int r = idx >> 2, u = idx & 3;
        int so = r * SROW + u * 8;
        *(uint4*)&sAh[so] = pA[q][0];
        *(uint4*)&sAl[so] = pA[q][1];
        *(uint4*)&sBh[so] = pB[q][0];
        *(uint4*)&sBl[so] = pB[q][1];
    }
    __syncthreads();

    for (int kc = 0; kc < NCH; kc++) {
        bool has = (kc + 1) < NCH;
        if (has) {
            int k0 = (kc + 1) * 32;
#pragma unroll
            for (int q = 0; q < 2; q++) {
                int idx = tid + q * 256;
                int r = idx >> 2, u = idx & 3;
                size_t ga = (size_t)(bm + r) * K + k0 + u * 8;
                size_t gb = (size_t)(bn + r) * K + k0 + u * 8;
                pA[q][0] = *(const uint4*)(Ah + ga);
                pA[q][1] = *(const uint4*)(Al + ga);
                pB[q][0] = *(const uint4*)(Bh + gb);
                pB[q][1] = *(const uint4*)(Bl + gb);
            }
        }
#pragma unroll
        for (int ks = 0; ks < 2; ks++) {
            int ar = wm * 64 + (lane >> 2);
            int ac = ks * 16 + (lane & 3) * 2;
            uint32_t ah[4][4], al[4][4], bh[4][2], bl[4][2];
#pragma unroll
            for (int mt = 0; mt < 4; mt++) {
                int r = ar + mt * 16;
                ah[mt][0] = lds32(&sAh[r * SROW + ac]);
                ah[mt][1] = lds32(&sAh[(r + 8) * SROW + ac]);
                ah[mt][2] = lds32(&sAh[r * SROW + ac + 8]);
                ah[mt][3] = lds32(&sAh[(r + 8) * SROW + ac + 8]);
                al[mt][0] = lds32(&sAl[r * SROW + ac]);
                al[mt][1] = lds32(&sAl[(r + 8) * SROW + ac]);
                al[mt][2] = lds32(&sAl[r * SROW + ac + 8]);
                al[mt][3] = lds32(&sAl[(r + 8) * SROW + ac + 8]);
            }
            int br = wn * 32 + (lane >> 2);
#pragma unroll
            for (int nt = 0; nt < 4; nt++) {
                int n = br + nt * 8;
                bh[nt][0] = lds32(&sBh[n * SROW + ac]);
                bh[nt][1] = lds32(&sBh[n * SROW + ac + 8]);
                bl[nt][0] = lds32(&sBl[n * SROW + ac]);
                bl[nt][1] = lds32(&sBl[n * SROW + ac + 8]);
            }
#pragma unroll
            for (int mt = 0; mt < 4; mt++)
#pragma unroll
                for (int nt = 0; nt < 4; nt++) {
                    mma_bf16(acc[mt][nt], ah[mt], bh[nt]);
                    mma_bf16(acc[mt][nt], ah[mt], bl[nt]);
                    mma_bf16(acc[mt][nt], al[mt], bh[nt]);
                }
        }
        __syncthreads();
        if (has) {
#pragma unroll
            for (int q = 0; q < 2; q++) {
                int idx = tid + q * 256;
                int r = idx >> 2, u = idx & 3;
                int so = r * SROW + u * 8;
                *(uint4*)&sAh[so] = pA[q][0];
                *(uint4*)&sAl[so] = pA[q][1];
                *(uint4*)&sBh[so] = pB[q][0];
                *(uint4*)&sBl[so] = pB[q][1];
            }
            __syncthreads();
        }
    }

    // ---- main output stores ----
#pragma unroll
    for (int mt = 0; mt < 4; mt++) {
#pragma unroll
        for (int nt = 0; nt < 4; nt++) {
            int r0 = bm + wm * 64 + mt * 16 + (lane >> 2);
            int c0 = bn + wn * 32 + nt * 8 + (lane & 3) * 2;
#pragma unroll
            for (int q = 0; q < 4; q++) {
                int row = r0 + (q >> 1) * 8;
                int col = c0 + (q & 1);
                float v = acc[mt][nt][q];
                if (bias) { v += bias[col]; acc[mt][nt][q] = v; }
                size_t o = (size_t)row * HH + col;
                if (Cf) Cf[o] = v;
                if (Chi) {
                    __nv_bfloat16 hb = __float2bfloat16(v);
                    Chi[o] = hb;
                    Clo[o] = __float2bfloat16(v - __bfloat162float(hb));
                }
                if (Cb) Cb[o] = __float2bfloat16(v);
            }
        }
    }

    // ---- fused attention-prep epilogue (layer GEMMs only) ----
    if (a_att) {
        float colp[8];
#pragma unroll
        for (int j = 0; j < 8; j++) colp[j] = 0.f;
#pragma unroll
        for (int mt = 0; mt < 4; mt++)
#pragma unroll
            for (int nt = 0; nt < 4; nt++)
#pragma unroll
                for (int q = 0; q < 4; q++)
                    colp[nt * 2 + (q & 1)] += acc[mt][nt][q];
#pragma unroll
        for (int off = 4; off <= 16; off <<= 1)
#pragma unroll
            for (int j = 0; j < 8; j++)
                colp[j] += __shfl_xor_sync(0xffffffffu, colp[j], off);

        float a_s[8], a_t[8];
#pragma unroll
        for (int nt = 0; nt < 4; nt++)
#pragma unroll
            for (int qb = 0; qb < 2; qb++) {
                int col = bn + wn * 32 + nt * 8 + (lane & 3) * 2 + qb;
                a_s[nt * 2 + qb] = __ldg(a_att + col);
                a_t[nt * 2 + qb] = __ldg(a_att + HH + col);
            }
        float rs_[8], rt_[8];
#pragma unroll
        for (int j = 0; j < 8; j++) { rs_[j] = 0.f; rt_[j] = 0.f; }
#pragma unroll
        for (int mt = 0; mt < 4; mt++)
#pragma unroll
            for (int nt = 0; nt < 4; nt++)
#pragma unroll
                for (int q = 0; q < 4; q++) {
                    float v = acc[mt][nt][q];
                    rs_[mt * 2 + (q >> 1)] += v * a_s[nt * 2 + (q & 1)];
                    rt_[mt * 2 + (q >> 1)] += v * a_t[nt * 2 + (q & 1)];
                }
#pragma unroll
        for (int off = 1; off <= 2; off <<= 1)
#pragma unroll
            for (int j = 0; j < 8; j++) {
                rs_[j] += __shfl_xor_sync(0xffffffffu, rs_[j], off);
                rt_[j] += __shfl_xor_sync(0xffffffffu, rt_[j], off);
            }

        float* sS = (float*)sAh;
        float* sT = sS + 512;
        float* sC = sT + 512;
        if ((lane & 3) == 0) {
#pragma unroll
            for (int mt = 0; mt < 4; mt++)
#pragma unroll
                for (int rq = 0; rq < 2; rq++) {
                    int row = wm * 64 + mt * 16 + rq * 8 + (lane >> 2);
                    sS[wn * 128 + row] = rs_[mt * 2 + rq];
                    sT[wn * 128 + row] = rt_[mt * 2 + rq];
                }
        }
        if (lane < 4) {
#pragma unroll
            for (int nt = 0; nt < 4; nt++)
#pragma unroll
                for (int qb = 0; qb < 2; qb++)
                    sC[wid * 32 + nt * 8 + (lane & 3) * 2 + qb] = colp[nt * 2 + qb];
        }
        __syncthreads();
        if (tid < 128) {
            float ss = sS[tid] + sS[128 + tid] + sS[256 + tid] + sS[384 + tid];
            float tt = sT[tid] + sT[128 + tid] + sT[256 + tid] + sT[384 + tid];
            g_s_srcp[blockIdx.y * NN + bm + tid] = ss;
            g_s_tgtp[blockIdx.y * NN + bm + tid] = tt;
            int wnc = tid >> 5, ci = tid & 31;
            float cv = sC[wnc * 32 + ci] + sC[(4 + wnc) * 32 + ci];
            g_colsum_part[blockIdx.x * HH + bn + tid] = cv;
        }
    }
}

// ---------------- prep: split x, split weights, zero counters ------------
__global__ void prep_kernel(const float* __restrict__ x,
                            const float* __restrict__ W_in,
                            const float* __restrict__ W_gat) {
    const int NW = D_IN * HH + NL * HH * HH;
    for (int i = blockIdx.x * blockDim.x + threadIdx.x; i < NN * D_IN;
         i += gridDim.x * blockDim.x) {
        float v = x[i];
        __nv_bfloat16 hb = __float2bfloat16(v);
        g_Ah[i] = hb;
        g_Al[i] = __float2bfloat16(v - __bfloat162float(hb));
        if (i < NW) {
            float w = (i < D_IN * HH) ? W_in[i] : W_gat[i - D_IN * HH];
            __nv_bfloat16 wb = __float2bfloat16(w);
            g_Bh[i] = wb;
            g_Bl[i] = __float2bfloat16(w - __bfloat162float(wb));
        }
        if (i < NN) g_cnt[i] = 0;
    }
}

// ---------------- bucket scatter + per-node sort --------------------------
__global__ void scatter_kernel(const int* __restrict__ ei) {
    const int* src = ei;
    const int* tgt = ei + EE;
    for (int k = blockIdx.x * blockDim.x + threadIdx.x; k < EE;
         k += gridDim.x * blockDim.x) {
        int s = src[k];
        int pos = atomicAdd(&g_cnt[s], 1);
        if (pos < BCAP) g_bkt[s * BCAP + pos] = tgt[k];
    }
}

// warp per node: odd-even transposition sort of the bucket (deterministic order)
__global__ __launch_bounds__(256)
void sort_bkt_kernel() {
    __shared__ int buf[8][BCAP];
    int wid = threadIdx.x >> 5, lane = threadIdx.x & 31;
    int i = blockIdx.x * 8 + wid;
    int deg = min(g_cnt[i], BCAP);
    for (int j = lane; j < deg; j += 32) buf[wid][j] = g_bkt[i * BCAP + j];
    __syncwarp();
    for (int p = 0; p < deg; p++) {
        int start = p & 1;
        for (int j = lane; 2 * j + start + 1 < deg; j += 32) {
            int a = buf[wid][2 * j + start], b = buf[wid][2 * j + start + 1];
            if (a > b) { buf[wid][2 * j + start] = b; buf[wid][2 * j + start + 1] = a; }
        }
        __syncwarp();
    }
    for (int j = lane; j < deg; j += 32) g_bkt[i * BCAP + j] = buf[wid][j];
}

// ---------------- colsum finalize + score combine (one kernel) ------------
__global__ void finalize_kernel() {
    if (blockIdx.x == 0) {
        int c = threadIdx.x;
        float s = 0.f;
#pragma unroll
        for (int b = 0; b < 64; b++) s += g_colsum_part[b * HH + c];
        g_colsum[c] = s;
    } else {
        int i = (blockIdx.x - 1) * 256 + threadIdx.x;
        g_s_src[i] = g_s_srcp[i] + g_s_srcp[NN + i];
        g_s_tgt[i] = g_s_tgtp[i] + g_s_tgtp[NN + i];
    }
}

// ---------------- warp-per-node aggregate + residual + LN + ELU ----------
__device__ __forceinline__ float4 unp_bf4u(uint32_t lo, uint32_t hi) {
    __nv_bfloat162 a = *reinterpret_cast<__nv_bfloat162*>(&lo);
    __nv_bfloat162 b = *reinterpret_cast<__nv_bfloat162*>(&hi);
    float2 fa = __bfloat1622float2(a), fb = __bfloat1622float2(b);
    return make_float4(fa.x, fa.y, fb.x, fb.y);
}

__global__ __launch_bounds__(256)
void aggregate_kernel(float* __restrict__ h,
                      const float* __restrict__ lng,
                      const float* __restrict__ lnb) {
    int wid = threadIdx.x >> 5, lane = threadIdx.x & 31;
    int i = blockIdx.x * 8 + wid;
    int deg = min(g_cnt[i], BCAP);
    float si = g_s_src[i];

    float4 a0 = make_float4(0.f, 0.f, 0.f, 0.f);
    float4 a1 = make_float4(0.f, 0.f, 0.f, 0.f);
    float wsum = 0.f;

    for (int base = 0; base < deg; base += 32) {
        int idx = base + lane;
        int tg = 0;
        float w = 0.f;
        if (idx < deg) {
            tg = g_bkt[i * BCAP + idx];
            float e = si + g_s_tgt[tg];
            e = (e > 0.f) ? e : 0.2f * e;
            w = expf(e) - 1.f;
        }
        float wr = w;
#pragma unroll
        for (int o = 16; o; o >>= 1) wr += __shfl_xor_sync(0xffffffffu, wr, o);
        wsum += wr;
        int len = min(32, deg - base);
        for (int k = 0; k < len; k++) {
            float wk = __shfl_sync(0xffffffffu, w, k);
            int   tk = __shfl_sync(0xffffffffu, tg, k);
            uint4 u = *((const uint4*)(g_hwb + (size_t)tk * HH) + lane);
            float4 v0 = unp_bf4u(u.x, u.y);
            float4 v1 = unp_bf4u(u.z, u.w);
            a0.x = fmaf(wk, v0.x, a0.x); a0.y = fmaf(wk, v0.y, a0.y);
            a0.z = fmaf(wk, v0.z, a0.z); a0.w = fmaf(wk, v0.w, a0.w);
            a1.x = fmaf(wk, v1.x, a1.x); a1.y = fmaf(wk, v1.y, a1.y);
            a1.z = fmaf(wk, v1.z, a1.z); a1.w = fmaf(wk, v1.w, a1.w);
        }
    }
    float denom = (float)NN + wsum;

    float4 cs0 = *((const float4*)g_colsum + lane * 2);
    float4 cs1 = *((const float4*)g_colsum + lane * 2 + 1);
    float4 h0 = *((const float4*)(h + (size_t)i * HH) + lane * 2);
    float4 h1 = *((const float4*)(h + (size_t)i * HH) + lane * 2 + 1);
    float4 v0, v1;
    v0.x = h0.x + (cs0.x + a0.x) / denom;
    v0.y = h0.y + (cs0.y + a0.y) / denom;
    v0.z = h0.z + (cs0.z + a0.z) / denom;
    v0.w = h0.w + (cs0.w + a0.w) / denom;
    v1.x = h1.x + (cs1.x + a1.x) / denom;
    v1.y = h1.y + (cs1.y + a1.y) / denom;
    v1.z = h1.z + (cs1.z + a1.z) / denom;
    v1.w = h1.w + (cs1.w + a1.w) / denom;

    float ts = v0.x + v0.y + v0.z + v0.w + v1.x + v1.y + v1.z + v1.w;
#pragma unroll
    for (int o = 16; o; o >>= 1) ts += __shfl_xor_sync(0xffffffffu, ts, o);
    float mu = ts / (float)HH;
    float d0x = v0.x - mu, d0y = v0.y - mu, d0z = v0.z - mu, d0w = v0.w - mu;
    float d1x = v1.x - mu, d1y = v1.y - mu, d1z = v1.z - mu, d1w = v1.w - mu;
    float tv = d0x * d0x + d0y * d0y + d0z * d0z + d0w * d0w
             + d1x * d1x + d1y * d1y + d1z * d1z + d1w * d1w;
#pragma unroll
    for (int o = 16; o; o >>= 1) tv += __shfl_xor_sync(0xffffffffu, tv, o);
    float rs = rsqrtf(tv / (float)HH + LN_EPS);

    float4 g0 = *((const float4*)lng + lane * 2);
    float4 g1 = *((const float4*)lng + lane * 2 + 1);
    float4 b0 = *((const float4*)lnb + lane * 2);
    float4 b1 = *((const float4*)lnb + lane * 2 + 1);
    float y[8];
    y[0] = d0x * rs * g0.x + b0.x; y[1] = d0y * rs * g0.y + b0.y;
    y[2] = d0z * rs * g0.z + b0.z; y[3] = d0w * rs * g0.w + b0.w;
    y[4] = d1x * rs * g1.x + b1.x; y[5] = d1y * rs * g1.y + b1.y;
    y[6] = d1z * rs * g1.z + b1.z; y[7] = d1w * rs * g1.w + b1.w;
#pragma unroll
    for (int j = 0; j < 8; j++) y[j] = (y[j] > 0.f) ? y[j] : (expf(y[j]) - 1.f);

    float4 o0 = make_float4(y[0], y[1], y[2], y[3]);
    float4 o1 = make_float4(y[4], y[5], y[6], y[7]);
    *((float4*)(h + (size_t)i * HH) + lane * 2)     = o0;
    *((float4*)(h + (size_t)i * HH) + lane * 2 + 1) = o1;

    uint32_t hiw[4], low[4];
#pragma unroll
    for (int p = 0; p < 4; p++) {
        __nv_bfloat16 h0b = __float2bfloat16(y[2 * p]);
        __nv_bfloat16 h1b = __float2bfloat16(y[2 * p + 1]);
        float l0 = y[2 * p] - __bfloat162float(h0b);
        float l1 = y[2 * p + 1] - __bfloat162float(h1b);
        __nv_bfloat162 hp = __nv_bfloat162(h0b, h1b);
        __nv_bfloat162 lp = __nv_bfloat162(__float2bfloat16(l0), __float2bfloat16(l1));
        hiw[p] = *reinterpret_cast<uint32_t*>(&hp);
        low[p] = *reinterpret_cast<uint32_t*>(&lp);
    }
    *((uint4*)(g_Ah2 + (size_t)i * HH) + lane) = make_uint4(hiw[0], hiw[1], hiw[2], hiw[3]);
    *((uint4*)(g_Al2 + (size_t)i * HH) + lane) = make_uint4(low[0], low[1], low[2], low[3]);
}

// ---------------- gated pooling ------------------------------------------
__global__ void pool1_kernel(const float* __restrict__ h,
                             const float* __restrict__ Wp,
                             const float* __restrict__ bp) {
    __shared__ float gates[128];
    int b = blockIdx.x;
    int t = threadIdx.x;
    int warp = t >> 5, lane = t & 31;
    int base = b * 128;
    for (int it = 0; it < 16; it++) {
        int n = base + warp * 16 + it;
        const float* row = h + (size_t)n * HH;
        float s = 0.f;
        for (int j = lane; j < HH; j += 32) s += row[j] * Wp[j];
#pragma unroll
        for (int o = 16; o; o >>= 1) s += __shfl_xor_sync(0xffffffffu, s, o);
        if (lane == 0) gates[warp * 16 + it] = 1.f / (1.f + expf(-(s + bp[0])));
    }
    __syncthreads();
    int c = t;
    float s = 0.f;
    for (int ln = 0; ln < 128; ln++)
        s = fmaf(gates[ln], h[(size_t)(base + ln) * HH + c], s);
    g_pool_part[b * HH + c] = s;
}
__global__ void pool2_kernel(float* __restrict__ emb) {
    int c = threadIdx.x;
    float s = 0.f;
#pragma unroll
    for (int b = 0; b < 64; b++) s += g_pool_part[b * HH + c];
    emb[c] = s;
}

// ---------------- launch --------------------------------------------------
extern "C" void kernel_launch(void* const* d_in, const int* in_sizes, int n_in,
                              void* d_out, int out_size) {
    const float* x      = (const float*)d_in[0];
    const int*   ei     = (const int*)d_in[1];
    const float* W_in   = (const float*)d_in[2];
    const float* b_in   = (const float*)d_in[3];
    const float* W_gat  = (const float*)d_in[4];
    const float* a_gat  = (const float*)d_in[5];
    const float* ln_g   = (const float*)d_in[6];
    const float* ln_b   = (const float*)d_in[7];
    const float* W_pool = (const float*)d_in[8];
    const float* b_pool = (const float*)d_in[9];

    float* out = (float*)d_out;
    float* h   = out;

    __nv_bfloat16 *Ah, *Al, *Ah2, *Al2, *Bh, *Bl, *hwb;
    cudaGetSymbolAddress((void**)&Ah,  g_Ah);
    cudaGetSymbolAddress((void**)&Al,  g_Al);
    cudaGetSymbolAddress((void**)&Ah2, g_Ah2);
    cudaGetSymbolAddress((void**)&Al2, g_Al2);
    cudaGetSymbolAddress((void**)&Bh,  g_Bh);
    cudaGetSymbolAddress((void**)&Bl,  g_Bl);
    cudaGetSymbolAddress((void**)&hwb, g_hwb);

    prep_kernel<<<2048, 256>>>(x, W_in, W_gat);
    scatter_kernel<<<256, 256>>>(ei);
    sort_bkt_kernel<<<NN / 8, 256>>>();

    // h = x @ W_in^T + b_in; emit h split for layer GEMMs
    gemm_mma<<<dim3(64, 2), 256>>>(Ah, Al, Bh, Bl, b_in, h, Ah2, Al2,
                                   (__nv_bfloat16*)nullptr, nullptr, D_IN);

    for (int l = 0; l < NL; l++) {
        const __nv_bfloat16* Wh = Bh + D_IN * HH + (size_t)l * HH * HH;
        const __nv_bfloat16* Wl = Bl + D_IN * HH + (size_t)l * HH * HH;
        gemm_mma<<<dim3(64, 2), 256>>>(Ah2, Al2, Wh, Wl, nullptr, nullptr,
                                       (__nv_bfloat16*)nullptr,
                                       (__nv_bfloat16*)nullptr, hwb,
                                       a_gat + (size_t)l * 2 * HH, HH);
        finalize_kernel<<<1 + NN / 256, 256>>>();
        aggregate_kernel<<<NN / 8, 256>>>(h, ln_g + (size_t)l * HH,
                                          ln_b + (size_t)l * HH);
    }

    pool1_kernel<<<64, 256>>>(h, W_pool, b_pool);
    pool2_kernel<<<1, 256>>>(out + (size_t)NN * HH);
}

// round 15
// speedup vs baseline: 2.9181x; 1.0621x over previous
#include <cuda_runtime.h>
#include <cuda_bf16.h>
#include <math.h>
#include <stdint.h>

// Problem constants
#define NN    8192
#define D_IN  512
#define HH    256
#define EE    262144
#define NL    2
#define LN_EPS 1e-5f
#define BCAP  128      // per-node bucket capacity (max deg ~60)

// ---------------- device scratch (no allocations allowed) ----------------
__device__ __nv_bfloat16 g_hwb[NN * HH];        // hw bf16 for gathers
__device__ __nv_bfloat16 g_Ah[NN * D_IN];       // x split hi
__device__ __nv_bfloat16 g_Al[NN * D_IN];       // x split lo
__device__ __nv_bfloat16 g_Ah2[NN * HH];        // h split hi
__device__ __nv_bfloat16 g_Al2[NN * HH];        // h split lo
__device__ __nv_bfloat16 g_Bh[D_IN * HH + NL * HH * HH];  // weights hi
__device__ __nv_bfloat16 g_Bl[D_IN * HH + NL * HH * HH];  // weights lo
__device__ float g_s_srcp[2 * NN];              // score partials (per N-half)
__device__ float g_s_tgtp[2 * NN];
__device__ float g_s_src[NN];                   // combined scores
__device__ float g_s_tgt[NN];
__device__ int   g_cnt[NN];
__device__ int   g_bkt[NN * BCAP];              // per-node target buckets
__device__ float g_colsum_part[64 * HH];        // per M-CTA column partials
__device__ float g_colsum[HH];
__device__ float g_pool_part[64 * HH];

// ---------------- HMMA GEMM: C[8192 x 256] = A * B^T ---------------------
// 512 threads, 16 warps (4x4 grid), warp tile 32x32. bf16 split inputs,
// 3 accumulating passes, fp32 accum. cp.async 2-stage pipeline, ldmatrix frags.
#define SROW   40                      // smem row stride (bf16 elems)
#define TILEB  (128 * SROW * 2)        // 10240 bytes per tile
#define STAGEB (4 * TILEB)             // 40960 bytes per stage
#define SMEM_DYN (2 * STAGEB)          // 81920 bytes

__device__ __forceinline__ uint32_t smem_u32(const void* p) {
    uint32_t a;
    asm("{ .reg .u64 t; cvta.to.shared.u64 t, %1; cvt.u32.u64 %0, t; }"
        : "=r"(a) : "l"(p));
    return a;
}
__device__ __forceinline__ void cp16(uint32_t saddr, const void* gptr) {
    asm volatile("cp.async.cg.shared.global [%0], [%1], 16;"
                 :: "r"(saddr), "l"(gptr));
}
#define CP_COMMIT() asm volatile("cp.async.commit_group;" ::: "memory")
#define CP_WAIT(n)  asm volatile("cp.async.wait_group %0;" :: "n"(n) : "memory")
__device__ __forceinline__ void ldsm4(uint32_t* r, uint32_t addr) {
    asm volatile("ldmatrix.sync.aligned.m8n8.x4.shared.b16 {%0,%1,%2,%3}, [%4];"
                 : "=r"(r[0]), "=r"(r[1]), "=r"(r[2]), "=r"(r[3]) : "r"(addr));
}
__device__ __forceinline__ void mma_bf16(float* d, const uint32_t* a, const uint32_t* b) {
    asm volatile(
        "mma.sync.aligned.m16n8k16.row.col.f32.bf16.bf16.f32 "
        "{%0,%1,%2,%3}, {%4,%5,%6,%7}, {%8,%9}, {%0,%1,%2,%3};"
        : "+f"(d[0]), "+f"(d[1]), "+f"(d[2]), "+f"(d[3])
        : "r"(a[0]), "r"(a[1]), "r"(a[2]), "r"(a[3]), "r"(b[0]), "r"(b[1]));
}

__global__ __launch_bounds__(512)
void gemm_mma(const __nv_bfloat16* __restrict__ Ah, const __nv_bfloat16* __restrict__ Al,
              const __nv_bfloat16* __restrict__ Bh, const __nv_bfloat16* __restrict__ Bl,
              const float* __restrict__ bias, float* __restrict__ Cf,
              __nv_bfloat16* __restrict__ Chi, __nv_bfloat16* __restrict__ Clo,
              __nv_bfloat16* __restrict__ Cb,
              const float* __restrict__ a_att,   // non-null => attn epilogue
              int K) {
    extern __shared__ char smem[];
    uint32_t sb = smem_u32(smem);
    int tid = threadIdx.x;
    int wid = tid >> 5, lane = tid & 31;
    int wm = wid >> 2, wn = wid & 3;          // 4x4 warp grid
    int bm = blockIdx.x * 128;
    int bn = blockIdx.y * 128;

    float acc[2][4][4];
#pragma unroll
    for (int mt = 0; mt < 2; mt++)
#pragma unroll
        for (int nt = 0; nt < 4; nt++)
#pragma unroll
            for (int q = 0; q < 4; q++) acc[mt][nt][q] = 0.f;

    const int NCH = K >> 5;

    // loader: 512 threads, 1x 16B per tile each (tile = 128 rows x 32 bf16)
    int lr = tid >> 2, lu = tid & 3;
    size_t gaB = (size_t)(bm + lr) * K + lu * 8;
    size_t gbB = (size_t)(bn + lr) * K + lu * 8;
    uint32_t soff = (uint32_t)(lr * SROW + lu * 8) * 2;

    // prologue: stage 0
    {
        cp16(sb + 0 * TILEB + soff, Ah + gaB);
        cp16(sb + 1 * TILEB + soff, Al + gaB);
        cp16(sb + 2 * TILEB + soff, Bh + gbB);
        cp16(sb + 3 * TILEB + soff, Bl + gbB);
        CP_COMMIT();
    }

    for (int kc = 0; kc < NCH; kc++) {
        bool has = (kc + 1) < NCH;
        if (has) {
            uint32_t st = sb + ((kc + 1) & 1) * STAGEB;
            int k0 = (kc + 1) * 32;
            cp16(st + 0 * TILEB + soff, Ah + gaB + k0);
            cp16(st + 1 * TILEB + soff, Al + gaB + k0);
            cp16(st + 2 * TILEB + soff, Bh + gbB + k0);
            cp16(st + 3 * TILEB + soff, Bl + gbB + k0);
            CP_COMMIT();
            CP_WAIT(1);
        } else {
            CP_WAIT(0);
        }
        __syncthreads();
        uint32_t st = sb + (kc & 1) * STAGEB;
#pragma unroll
        for (int ks = 0; ks < 2; ks++) {
            int ac = ks * 16;
            uint32_t ah[2][4], al[2][4], bh[4][2], bl[4][2];
            // A fragments via ldmatrix.x4 (m0..m3 = (r,ac),(r+8,ac),(r,ac+8),(r+8,ac+8))
            {
                int arow = (lane & 15);
                int acol = ac + (lane >> 4) * 8;
#pragma unroll
                for (int mt = 0; mt < 2; mt++) {
                    int r = wm * 32 + mt * 16 + arow;
                    uint32_t off = (uint32_t)(r * SROW + acol) * 2;
                    ldsm4(ah[mt], st + 0 * TILEB + off);
                    ldsm4(al[mt], st + 1 * TILEB + off);
                }
            }
            // B fragments: one x4 covers nt pair {2np, 2np+1}
            {
                int brow = ((lane >> 4) & 1) * 8 + (lane & 7);
                int bcol = ac + ((lane >> 3) & 1) * 8;
#pragma unroll
                for (int np = 0; np < 2; np++) {
                    int n = wn * 32 + np * 16 + brow;
                    uint32_t off = (uint32_t)(n * SROW + bcol) * 2;
                    uint32_t t4[4];
                    ldsm4(t4, st + 2 * TILEB + off);
                    bh[2 * np][0] = t4[0]; bh[2 * np][1] = t4[1];
                    bh[2 * np + 1][0] = t4[2]; bh[2 * np + 1][1] = t4[3];
                    ldsm4(t4, st + 3 * TILEB + off);
                    bl[2 * np][0] = t4[0]; bl[2 * np][1] = t4[1];
                    bl[2 * np + 1][0] = t4[2]; bl[2 * np + 1][1] = t4[3];
                }
            }
#pragma unroll
            for (int mt = 0; mt < 2; mt++)
#pragma unroll
                for (int nt = 0; nt < 4; nt++) {
                    mma_bf16(acc[mt][nt], ah[mt], bh[nt]);
                    mma_bf16(acc[mt][nt], ah[mt], bl[nt]);
                    mma_bf16(acc[mt][nt], al[mt], bh[nt]);
                }
        }
        __syncthreads();
    }

    // ---- main output stores ----
#pragma unroll
    for (int mt = 0; mt < 2; mt++) {
#pragma unroll
        for (int nt = 0; nt < 4; nt++) {
            int r0 = bm + wm * 32 + mt * 16 + (lane >> 2);
            int c0 = bn + wn * 32 + nt * 8 + (lane & 3) * 2;
#pragma unroll
            for (int q = 0; q < 4; q++) {
                int row = r0 + (q >> 1) * 8;
                int col = c0 + (q & 1);
                float v = acc[mt][nt][q];
                if (bias) { v += bias[col]; acc[mt][nt][q] = v; }
                size_t o = (size_t)row * HH + col;
                if (Cf) Cf[o] = v;
                if (Chi) {
                    __nv_bfloat16 hb = __float2bfloat16(v);
                    Chi[o] = hb;
                    Clo[o] = __float2bfloat16(v - __bfloat162float(hb));
                }
                if (Cb) Cb[o] = __float2bfloat16(v);
            }
        }
    }

    // ---- fused attention-prep epilogue (layer GEMMs only) ----
    if (a_att) {
        float colp[8];
#pragma unroll
        for (int j = 0; j < 8; j++) colp[j] = 0.f;
#pragma unroll
        for (int mt = 0; mt < 2; mt++)
#pragma unroll
            for (int nt = 0; nt < 4; nt++)
#pragma unroll
                for (int q = 0; q < 4; q++)
                    colp[nt * 2 + (q & 1)] += acc[mt][nt][q];
#pragma unroll
        for (int off = 4; off <= 16; off <<= 1)
#pragma unroll
            for (int j = 0; j < 8; j++)
                colp[j] += __shfl_xor_sync(0xffffffffu, colp[j], off);

        float a_s[8], a_t[8];
#pragma unroll
        for (int nt = 0; nt < 4; nt++)
#pragma unroll
            for (int qb = 0; qb < 2; qb++) {
                int col = bn + wn * 32 + nt * 8 + (lane & 3) * 2 + qb;
                a_s[nt * 2 + qb] = __ldg(a_att + col);
                a_t[nt * 2 + qb] = __ldg(a_att + HH + col);
            }
        float rs_[4], rt_[4];
#pragma unroll
        for (int j = 0; j < 4; j++) { rs_[j] = 0.f; rt_[j] = 0.f; }
#pragma unroll
        for (int mt = 0; mt < 2; mt++)
#pragma unroll
            for (int nt = 0; nt < 4; nt++)
#pragma unroll
                for (int q = 0; q < 4; q++) {
                    float v = acc[mt][nt][q];
                    rs_[mt * 2 + (q >> 1)] += v * a_s[nt * 2 + (q & 1)];
                    rt_[mt * 2 + (q >> 1)] += v * a_t[nt * 2 + (q & 1)];
                }
#pragma unroll
        for (int off = 1; off <= 2; off <<= 1)
#pragma unroll
            for (int j = 0; j < 4; j++) {
                rs_[j] += __shfl_xor_sync(0xffffffffu, rs_[j], off);
                rt_[j] += __shfl_xor_sync(0xffffffffu, rt_[j], off);
            }

        // stage in stage-0 smem (last compute used stage 1; NCH even)
        float* sS = (float*)smem;            // [4 wn][128 rows]
        float* sT = sS + 512;
        float* sC = sT + 512;                // [16 wid][32]
        if ((lane & 3) == 0) {
#pragma unroll
            for (int mt = 0; mt < 2; mt++)
#pragma unroll
                for (int rq = 0; rq < 2; rq++) {
                    int row = wm * 32 + mt * 16 + rq * 8 + (lane >> 2);
                    sS[wn * 128 + row] = rs_[mt * 2 + rq];
                    sT[wn * 128 + row] = rt_[mt * 2 + rq];
                }
        }
        if (lane < 4) {
#pragma unroll
            for (int nt = 0; nt < 4; nt++)
#pragma unroll
                for (int qb = 0; qb < 2; qb++)
                    sC[wid * 32 + nt * 8 + lane * 2 + qb] = colp[nt * 2 + qb];
        }
        __syncthreads();
        if (tid < 128) {
            float ss = sS[tid] + sS[128 + tid] + sS[256 + tid] + sS[384 + tid];
            float tt = sT[tid] + sT[128 + tid] + sT[256 + tid] + sT[384 + tid];
            g_s_srcp[blockIdx.y * NN + bm + tid] = ss;
            g_s_tgtp[blockIdx.y * NN + bm + tid] = tt;
            int wnc = tid >> 5, ci = tid & 31;
            float cv = sC[(0 * 4 + wnc) * 32 + ci] + sC[(1 * 4 + wnc) * 32 + ci]
                     + sC[(2 * 4 + wnc) * 32 + ci] + sC[(3 * 4 + wnc) * 32 + ci];
            g_colsum_part[blockIdx.x * HH + bn + tid] = cv;
        }
    }
}

// ---------------- prep: split x, split weights, zero counters ------------
__global__ void prep_kernel(const float* __restrict__ x,
                            const float* __restrict__ W_in,
                            const float* __restrict__ W_gat) {
    const int NW = D_IN * HH + NL * HH * HH;
    for (int i = blockIdx.x * blockDim.x + threadIdx.x; i < NN * D_IN;
         i += gridDim.x * blockDim.x) {
        float v = x[i];
        __nv_bfloat16 hb = __float2bfloat16(v);
        g_Ah[i] = hb;
        g_Al[i] = __float2bfloat16(v - __bfloat162float(hb));
        if (i < NW) {
            float w = (i < D_IN * HH) ? W_in[i] : W_gat[i - D_IN * HH];
            __nv_bfloat16 wb = __float2bfloat16(w);
            g_Bh[i] = wb;
            g_Bl[i] = __float2bfloat16(w - __bfloat162float(wb));
        }
        if (i < NN) g_cnt[i] = 0;
    }
}

// ---------------- bucket scatter + per-node sort --------------------------
__global__ void scatter_kernel(const int* __restrict__ ei) {
    const int* src = ei;
    const int* tgt = ei + EE;
    for (int k = blockIdx.x * blockDim.x + threadIdx.x; k < EE;
         k += gridDim.x * blockDim.x) {
        int s = src[k];
        int pos = atomicAdd(&g_cnt[s], 1);
        if (pos < BCAP) g_bkt[s * BCAP + pos] = tgt[k];
    }
}

__global__ __launch_bounds__(256)
void sort_bkt_kernel() {
    __shared__ int buf[8][BCAP];
    int wid = threadIdx.x >> 5, lane = threadIdx.x & 31;
    int i = blockIdx.x * 8 + wid;
    int deg = min(g_cnt[i], BCAP);
    for (int j = lane; j < deg; j += 32) buf[wid][j] = g_bkt[i * BCAP + j];
    __syncwarp();
    for (int p = 0; p < deg; p++) {
        int start = p & 1;
        for (int j = lane; 2 * j + start + 1 < deg; j += 32) {
            int a = buf[wid][2 * j + start], b = buf[wid][2 * j + start + 1];
            if (a > b) { buf[wid][2 * j + start] = b; buf[wid][2 * j + start + 1] = a; }
        }
        __syncwarp();
    }
    for (int j = lane; j < deg; j += 32) g_bkt[i * BCAP + j] = buf[wid][j];
}

// ---------------- colsum finalize + score combine (one kernel) ------------
__global__ void finalize_kernel() {
    if (blockIdx.x == 0) {
        int c = threadIdx.x;
        float s = 0.f;
#pragma unroll
        for (int b = 0; b < 64; b++) s += g_colsum_part[b * HH + c];
        g_colsum[c] = s;
    } else {
        int i = (blockIdx.x - 1) * 256 + threadIdx.x;
        g_s_src[i] = g_s_srcp[i] + g_s_srcp[NN + i];
        g_s_tgt[i] = g_s_tgtp[i] + g_s_tgtp[NN + i];
    }
}

// ---------------- warp-per-node aggregate + residual + LN + ELU ----------
__device__ __forceinline__ float4 unp_bf4u(uint32_t lo, uint32_t hi) {
    __nv_bfloat162 a = *reinterpret_cast<__nv_bfloat162*>(&lo);
    __nv_bfloat162 b = *reinterpret_cast<__nv_bfloat162*>(&hi);
    float2 fa = __bfloat1622float2(a), fb = __bfloat1622float2(b);
    return make_float4(fa.x, fa.y, fb.x, fb.y);
}

__global__ __launch_bounds__(256)
void aggregate_kernel(float* __restrict__ h,
                      const float* __restrict__ lng,
                      const float* __restrict__ lnb) {
    int wid = threadIdx.x >> 5, lane = threadIdx.x & 31;
    int i = blockIdx.x * 8 + wid;
    int deg = min(g_cnt[i], BCAP);
    float si = g_s_src[i];

    float4 a0 = make_float4(0.f, 0.f, 0.f, 0.f);
    float4 a1 = make_float4(0.f, 0.f, 0.f, 0.f);
    float wsum = 0.f;

    for (int base = 0; base < deg; base += 32) {
        int idx = base + lane;
        int tg = 0;
        float w = 0.f;
        if (idx < deg) {
            tg = g_bkt[i * BCAP + idx];
            float e = si + g_s_tgt[tg];
            e = (e > 0.f) ? e : 0.2f * e;
            w = expf(e) - 1.f;
        }
        float wr = w;
#pragma unroll
        for (int o = 16; o; o >>= 1) wr += __shfl_xor_sync(0xffffffffu, wr, o);
        wsum += wr;
        int len = min(32, deg - base);
        for (int k = 0; k < len; k++) {
            float wk = __shfl_sync(0xffffffffu, w, k);
            int   tk = __shfl_sync(0xffffffffu, tg, k);
            uint4 u = *((const uint4*)(g_hwb + (size_t)tk * HH) + lane);
            float4 v0 = unp_bf4u(u.x, u.y);
            float4 v1 = unp_bf4u(u.z, u.w);
            a0.x = fmaf(wk, v0.x, a0.x); a0.y = fmaf(wk, v0.y, a0.y);
            a0.z = fmaf(wk, v0.z, a0.z); a0.w = fmaf(wk, v0.w, a0.w);
            a1.x = fmaf(wk, v1.x, a1.x); a1.y = fmaf(wk, v1.y, a1.y);
            a1.z = fmaf(wk, v1.z, a1.z); a1.w = fmaf(wk, v1.w, a1.w);
        }
    }
    float denom = (float)NN + wsum;

    float4 cs0 = *((const float4*)g_colsum + lane * 2);
    float4 cs1 = *((const float4*)g_colsum + lane * 2 + 1);
    float4 h0 = *((const float4*)(h + (size_t)i * HH) + lane * 2);
    float4 h1 = *((const float4*)(h + (size_t)i * HH) + lane * 2 + 1);
    float4 v0, v1;
    v0.x = h0.x + (cs0.x + a0.x) / denom;
    v0.y = h0.y + (cs0.y + a0.y) / denom;
    v0.z = h0.z + (cs0.z + a0.z) / denom;
    v0.w = h0.w + (cs0.w + a0.w) / denom;
    v1.x = h1.x + (cs1.x + a1.x) / denom;
    v1.y = h1.y + (cs1.y + a1.y) / denom;
    v1.z = h1.z + (cs1.z + a1.z) / denom;
    v1.w = h1.w + (cs1.w + a1.w) / denom;

    float ts = v0.x + v0.y + v0.z + v0.w + v1.x + v1.y + v1.z + v1.w;
#pragma unroll
    for (int o = 16; o; o >>= 1) ts += __shfl_xor_sync(0xffffffffu, ts, o);
    float mu = ts / (float)HH;
    float d0x = v0.x - mu, d0y = v0.y - mu, d0z = v0.z - mu, d0w = v0.w - mu;
    float d1x = v1.x - mu, d1y = v1.y - mu, d1z = v1.z - mu, d1w = v1.w - mu;
    float tv = d0x * d0x + d0y * d0y + d0z * d0z + d0w * d0w
             + d1x * d1x + d1y * d1y + d1z * d1z + d1w * d1w;
#pragma unroll
    for (int o = 16; o; o >>= 1) tv += __shfl_xor_sync(0xffffffffu, tv, o);
    float rs = rsqrtf(tv / (float)HH + LN_EPS);

    float4 g0 = *((const float4*)lng + lane * 2);
    float4 g1 = *((const float4*)lng + lane * 2 + 1);
    float4 b0 = *((const float4*)lnb + lane * 2);
    float4 b1 = *((const float4*)lnb + lane * 2 + 1);
    float y[8];
    y[0] = d0x * rs * g0.x + b0.x; y[1] = d0y * rs * g0.y + b0.y;
    y[2] = d0z * rs * g0.z + b0.z; y[3] = d0w * rs * g0.w + b0.w;
    y[4] = d1x * rs * g1.x + b1.x; y[5] = d1y * rs * g1.y + b1.y;
    y[6] = d1z * rs * g1.z + b1.z; y[7] = d1w * rs * g1.w + b1.w;
#pragma unroll
    for (int j = 0; j < 8; j++) y[j] = (y[j] > 0.f) ? y[j] : (expf(y[j]) - 1.f);

    float4 o0 = make_float4(y[0], y[1], y[2], y[3]);
    float4 o1 = make_float4(y[4], y[5], y[6], y[7]);
    *((float4*)(h + (size_t)i * HH) + lane * 2)     = o0;
    *((float4*)(h + (size_t)i * HH) + lane * 2 + 1) = o1;

    uint32_t hiw[4], low[4];
#pragma unroll
    for (int p = 0; p < 4; p++) {
        __nv_bfloat16 h0b = __float2bfloat16(y[2 * p]);
        __nv_bfloat16 h1b = __float2bfloat16(y[2 * p + 1]);
        float l0 = y[2 * p] - __bfloat162float(h0b);
        float l1 = y[2 * p + 1] - __bfloat162float(h1b);
        __nv_bfloat162 hp = __nv_bfloat162(h0b, h1b);
        __nv_bfloat162 lp = __nv_bfloat162(__float2bfloat16(l0), __float2bfloat16(l1));
        hiw[p] = *reinterpret_cast<uint32_t*>(&hp);
        low[p] = *reinterpret_cast<uint32_t*>(&lp);
    }
    *((uint4*)(g_Ah2 + (size_t)i * HH) + lane) = make_uint4(hiw[0], hiw[1], hiw[2], hiw[3]);
    *((uint4*)(g_Al2 + (size_t)i * HH) + lane) = make_uint4(low[0], low[1], low[2], low[3]);
}

// ---------------- gated pooling ------------------------------------------
__global__ void pool1_kernel(const float* __restrict__ h,
                             const float* __restrict__ Wp,
                             const float* __restrict__ bp) {
    __shared__ float gates[128];
    int b = blockIdx.x;
    int t = threadIdx.x;
    int warp = t >> 5, lane = t & 31;
    int base = b * 128;
    for (int it = 0; it < 16; it++) {
        int n = base + warp * 16 + it;
        const float* row = h + (size_t)n * HH;
        float s = 0.f;
        for (int j = lane; j < HH; j += 32) s += row[j] * Wp[j];
#pragma unroll
        for (int o = 16; o; o >>= 1) s += __shfl_xor_sync(0xffffffffu, s, o);
        if (lane == 0) gates[warp * 16 + it] = 1.f / (1.f + expf(-(s + bp[0])));
    }
    __syncthreads();
    int c = t;
    float s = 0.f;
    for (int ln = 0; ln < 128; ln++)
        s = fmaf(gates[ln], h[(size_t)(base + ln) * HH + c], s);
    g_pool_part[b * HH + c] = s;
}
__global__ void pool2_kernel(float* __restrict__ emb) {
    int c = threadIdx.x;
    float s = 0.f;
#pragma unroll
    for (int b = 0; b < 64; b++) s += g_pool_part[b * HH + c];
    emb[c] = s;
}

// ---------------- launch --------------------------------------------------
extern "C" void kernel_launch(void* const* d_in, const int* in_sizes, int n_in,
                              void* d_out, int out_size) {
    const float* x      = (const float*)d_in[0];
    const int*   ei     = (const int*)d_in[1];
    const float* W_in   = (const float*)d_in[2];
    const float* b_in   = (const float*)d_in[3];
    const float* W_gat  = (const float*)d_in[4];
    const float* a_gat  = (const float*)d_in[5];
    const float* ln_g   = (const float*)d_in[6];
    const float* ln_b   = (const float*)d_in[7];
    const float* W_pool = (const float*)d_in[8];
    const float* b_pool = (const float*)d_in[9];

    float* out = (float*)d_out;
    float* h   = out;

    __nv_bfloat16 *Ah, *Al, *Ah2, *Al2, *Bh, *Bl, *hwb;
    cudaGetSymbolAddress((void**)&Ah,  g_Ah);
    cudaGetSymbolAddress((void**)&Al,  g_Al);
    cudaGetSymbolAddress((void**)&Ah2, g_Ah2);
    cudaGetSymbolAddress((void**)&Al2, g_Al2);
    cudaGetSymbolAddress((void**)&Bh,  g_Bh);
    cudaGetSymbolAddress((void**)&Bl,  g_Bl);
    cudaGetSymbolAddress((void**)&hwb, g_hwb);

    cudaFuncSetAttribute(gemm_mma, cudaFuncAttributeMaxDynamicSharedMemorySize, SMEM_DYN);

    prep_kernel<<<2048, 256>>>(x, W_in, W_gat);
    scatter_kernel<<<256, 256>>>(ei);
    sort_bkt_kernel<<<NN / 8, 256>>>();

    // h = x @ W_in^T + b_in; emit h split for layer GEMMs
    gemm_mma<<<dim3(64, 2), 512, SMEM_DYN>>>(Ah, Al, Bh, Bl, b_in, h, Ah2, Al2,
                                             (__nv_bfloat16*)nullptr, nullptr, D_IN);

    for (int l = 0; l < NL; l++) {
        const __nv_bfloat16* Wh = Bh + D_IN * HH + (size_t)l * HH * HH;
        const __nv_bfloat16* Wl = Bl + D_IN * HH + (size_t)l * HH * HH;
        gemm_mma<<<dim3(64, 2), 512, SMEM_DYN>>>(Ah2, Al2, Wh, Wl, nullptr, nullptr,
                                                 (__nv_bfloat16*)nullptr,
                                                 (__nv_bfloat16*)nullptr, hwb,
                                                 a_gat + (size_t)l * 2 * HH, HH);
        finalize_kernel<<<1 + NN / 256, 256>>>();
        aggregate_kernel<<<NN / 8, 256>>>(h, ln_g + (size_t)l * HH,
                                          ln_b + (size_t)l * HH);
    }

    pool1_kernel<<<64, 256>>>(h, W_pool, b_pool);
    pool2_kernel<<<1, 256>>>(out + (size_t)NN * HH);
}